// round 12
// baseline (speedup 1.0000x reference)
#include <cuda_runtime.h>
#include <cuda_bf16.h>
#include <cuda_fp16.h>
#include <cstdint>

#define HH 128
#define WW 128
#define HWS 16384
#define NB 4
#define KP 512   // split-K storage: [hi(256) | lo(256)]; 12 virtual chunks at GEMM

// ---------------- scratch (device globals; allocation-free rule) ------------
__device__ __align__(16) __nv_bfloat16 g_qhi[(size_t)NB * 32 * HWS];
__device__ __align__(16) __nv_bfloat16 g_qlo[(size_t)NB * 32 * HWS];
__device__ __align__(16) __nv_bfloat16 g_khi[(size_t)NB * 32 * HWS];
__device__ __align__(16) __nv_bfloat16 g_klo[(size_t)NB * 32 * HWS];
__device__ __align__(16) __nv_bfloat16 g_qhiT[(size_t)NB * 32 * HWS];
__device__ __align__(16) __nv_bfloat16 g_qloT[(size_t)NB * 32 * HWS];
__device__ __align__(16) __nv_bfloat16 g_khiT[(size_t)NB * 32 * HWS];
__device__ __align__(16) __nv_bfloat16 g_kloT[(size_t)NB * 32 * HWS];
__device__ __align__(16) __half g_v [(size_t)NB * 256 * HWS];
__device__ __align__(16) __half g_vT[(size_t)NB * 256 * HWS];
__device__ __align__(16) __nv_bfloat16 g_wsplit[(size_t)384 * KP];       // [m][hi|lo]
__device__ __align__(16) __nv_bfloat16 g_xt[(size_t)NB * HWS * KP];      // [b][p][hi|lo]

// single TU-wide dynamic smem symbol (char; cast per-kernel)
extern __shared__ __align__(1024) char smem_raw[];

static __device__ __forceinline__ uint32_t sw128(uint32_t off) {
    return off ^ ((off >> 3) & 0x70);
}
static __device__ __forceinline__ uint32_t sw256(uint32_t off) {
    return off ^ (((off >> 8) & 7) << 4);
}
__device__ __forceinline__ uint32_t smem_u32(const void* p) {
    uint32_t a;
    asm("{ .reg .u64 t; cvta.to.shared.u64 t, %1; cvt.u32.u64 %0, t; }"
        : "=r"(a) : "l"(p));
    return a;
}
__device__ __forceinline__ void ldmatrix_x4(uint32_t& r0, uint32_t& r1,
                                            uint32_t& r2, uint32_t& r3, uint32_t addr) {
    asm volatile("ldmatrix.sync.aligned.m8n8.x4.shared.b16 {%0,%1,%2,%3}, [%4];"
                 : "=r"(r0), "=r"(r1), "=r"(r2), "=r"(r3) : "r"(addr));
}
__device__ __forceinline__ void ldmatrix_x4_trans(uint32_t& r0, uint32_t& r1,
                                                  uint32_t& r2, uint32_t& r3, uint32_t addr) {
    asm volatile("ldmatrix.sync.aligned.m8n8.x4.trans.shared.b16 {%0,%1,%2,%3}, [%4];"
                 : "=r"(r0), "=r"(r1), "=r"(r2), "=r"(r3) : "r"(addr));
}
__device__ __forceinline__ void mma_bf16(float& d0, float& d1, float& d2, float& d3,
                                         uint32_t a0, uint32_t a1, uint32_t a2, uint32_t a3,
                                         uint32_t b0, uint32_t b1) {
    asm volatile("mma.sync.aligned.m16n8k16.row.col.f32.bf16.bf16.f32 "
                 "{%0,%1,%2,%3}, {%4,%5,%6,%7}, {%8,%9}, {%0,%1,%2,%3};"
                 : "+f"(d0), "+f"(d1), "+f"(d2), "+f"(d3)
                 : "r"(a0), "r"(a1), "r"(a2), "r"(a3), "r"(b0), "r"(b1));
}
__device__ __forceinline__ void mma_f16(float& d0, float& d1, float& d2, float& d3,
                                        uint32_t a0, uint32_t a1, uint32_t a2, uint32_t a3,
                                        uint32_t b0, uint32_t b1) {
    asm volatile("mma.sync.aligned.m16n8k16.row.col.f32.f16.f16.f32 "
                 "{%0,%1,%2,%3}, {%4,%5,%6,%7}, {%8,%9}, {%0,%1,%2,%3};"
                 : "+f"(d0), "+f"(d1), "+f"(d2), "+f"(d3)
                 : "r"(a0), "r"(a1), "r"(a2), "r"(a3), "r"(b0), "r"(b1));
}
#define CP_ASYNC16(dst, src) \
    asm volatile("cp.async.cg.shared.global [%0], [%1], 16;" :: "r"(dst), "l"(src))
#define CP_COMMIT() asm volatile("cp.async.commit_group;" ::: "memory")
#define CP_WAIT2()  asm volatile("cp.async.wait_group 2;" ::: "memory")
#define CP_WAIT1()  asm volatile("cp.async.wait_group 1;" ::: "memory")
#define CP_WAIT0()  asm volatile("cp.async.wait_group 0;" ::: "memory")

// ---------------------------------------------------------------------------
// prep_w: W' bf16 [384][512]; rows 0-255 Wv, 256-287 Wq, 288-319 Wk, 320-383 0
// ---------------------------------------------------------------------------
__global__ void prep_w_kernel(const float* __restrict__ Wq, const float* __restrict__ Wk,
                              const float* __restrict__ Wv)
{
    const int m = blockIdx.x;
    const int c = threadIdx.x;
    float w = 0.0f;
    if (m < 256)      w = Wv[m * 256 + c];
    else if (m < 288) w = Wq[(m - 256) * 256 + c];
    else if (m < 320) w = Wk[(m - 288) * 256 + c];
    __nv_bfloat16 hi = __float2bfloat16(w);
    __nv_bfloat16 lo = __float2bfloat16(w - __bfloat162float(hi));
    g_wsplit[(size_t)m * KP + c]       = hi;
    g_wsplit[(size_t)m * KP + 256 + c] = lo;
}

// ---------------------------------------------------------------------------
// prep_x: XT' bf16 [b][p][512]: cols [0:256)=hi, [256:512)=lo
// ---------------------------------------------------------------------------
__global__ void prep_x_kernel(const float* __restrict__ x)
{
    __shared__ float sm[64][65];
    const int b = blockIdx.z, ct = blockIdx.y, pt = blockIdx.x;
    const int c0 = ct * 64, p0 = pt * 64;
    const int t = threadIdx.x;
    const int pj = t & 63, ci0 = t >> 6;
    const float* xb = x + ((size_t)b * 256 + c0) * HWS + p0;
    #pragma unroll
    for (int i = 0; i < 16; i++) {
        int ci = ci0 + i * 4;
        sm[ci][pj] = xb[(size_t)ci * HWS + pj];
    }
    __syncthreads();
    const int cp = t & 31, pl = t >> 5;
    #pragma unroll
    for (int i = 0; i < 8; i++) {
        int p = pl + i * 8;
        float f0 = sm[2 * cp][p], f1 = sm[2 * cp + 1][p];
        __nv_bfloat16 h0 = __float2bfloat16(f0), h1 = __float2bfloat16(f1);
        __nv_bfloat16 l0 = __float2bfloat16(f0 - __bfloat162float(h0));
        __nv_bfloat16 l1 = __float2bfloat16(f1 - __bfloat162float(h1));
        __nv_bfloat162 hp; hp.x = h0; hp.y = h1;
        __nv_bfloat162 lp; lp.x = l0; lp.y = l1;
        __nv_bfloat16* row = g_xt + ((size_t)b * HWS + p0 + p) * KP;
        *(__nv_bfloat162*)(row + c0 + 2 * cp)       = hp;
        *(__nv_bfloat162*)(row + 256 + c0 + 2 * cp) = lp;
    }
}

// ---------------------------------------------------------------------------
// proj_mma: 3-stage cp.async ring, ONE sync per iteration.
// Stage write at iter ch targets (ch+2)%3, last read at iter ch-1; issuing
// AFTER the iteration-top barrier makes that WAR-safe without a second sync.
// dyn smem: stage s at s*32768: A [0,16K), B [16K,32K). 96K total.
// ---------------------------------------------------------------------------
__constant__ int ACH[12] = {0, 1, 2, 3, 0, 1, 2, 3, 4, 5, 6, 7};
__constant__ int BCH[12] = {0, 1, 2, 3, 4, 5, 6, 7, 0, 1, 2, 3};

__global__ void __launch_bounds__(256) proj_mma_kernel(
    const float* __restrict__ bq, const float* __restrict__ bk,
    const float* __restrict__ bv)
{
    char* smem = smem_raw;
    const uint32_t smem_base = smem_u32(smem);
    const int tid = threadIdx.x;
    const int wid = tid >> 5, lane = tid & 31;
    const int warp_m = wid & 1;
    const int warp_n = wid >> 1;
    const int pt = blockIdx.x, mt = blockIdx.y, b = blockIdx.z;
    const bool mma_active = (mt < 2) || (warp_m == 0);

    const char* Abase = (const char*)(g_wsplit + (size_t)mt * 128 * KP);
    const char* Bbase = (const char*)(g_xt + ((size_t)b * HWS + pt * 128) * KP);

    float acc[4][4][4];
    #pragma unroll
    for (int i = 0; i < 4; i++)
        #pragma unroll
        for (int j = 0; j < 4; j++)
            #pragma unroll
            for (int k = 0; k < 4; k++) acc[i][j][k] = 0.0f;

    const int a_row_in = lane & 15;
    const int a_kseg   = (lane >> 4) << 4;
    const int b_row_in = (lane & 7) + ((lane >> 4) << 3);
    const int b_kseg   = ((lane >> 3) & 1) << 4;

    const int ld_row = tid >> 3, ld_seg = tid & 7;

    auto issue = [&](int ch, int st) {
        const size_t a0b = (size_t)ACH[ch] * 128;
        const size_t b0b = (size_t)BCH[ch] * 128;
        const uint32_t sb = smem_base + st * 32768;
        #pragma unroll
        for (int r = 0; r < 4; r++) {
            int row = ld_row + r * 32;
            uint32_t so = sw128((uint32_t)(row * 128 + ld_seg * 16));
            CP_ASYNC16(sb + so,         Abase + (size_t)row * (KP * 2) + a0b + ld_seg * 16);
            CP_ASYNC16(sb + 16384 + so, Bbase + (size_t)row * (KP * 2) + b0b + ld_seg * 16);
        }
    };

    issue(0, 0); CP_COMMIT();
    issue(1, 1); CP_COMMIT();

    for (int ch = 0; ch < 12; ch++) {
        const int st = ch % 3;
        if (ch == 11) { CP_WAIT0(); } else { CP_WAIT1(); }
        __syncthreads();
        if (ch + 2 < 12) { issue(ch + 2, (ch + 2) % 3); CP_COMMIT(); }

        if (mma_active) {
            const uint32_t sA_u = smem_base + st * 32768;
            const uint32_t sB_u = sA_u + 16384;
            #pragma unroll
            for (int kk = 0; kk < 4; kk++) {
                uint32_t af[4][4];
                #pragma unroll
                for (int mi = 0; mi < 4; mi++) {
                    int row = warp_m * 64 + mi * 16 + a_row_in;
                    ldmatrix_x4(af[mi][0], af[mi][1], af[mi][2], af[mi][3],
                                sA_u + sw128((uint32_t)(row * 128 + kk * 32 + a_kseg)));
                }
                uint32_t bf[2][4];
                #pragma unroll
                for (int ni16 = 0; ni16 < 2; ni16++) {
                    int row = warp_n * 32 + ni16 * 16 + b_row_in;
                    ldmatrix_x4(bf[ni16][0], bf[ni16][1], bf[ni16][2], bf[ni16][3],
                                sB_u + sw128((uint32_t)(row * 128 + kk * 32 + b_kseg)));
                }
                #pragma unroll
                for (int mi = 0; mi < 4; mi++)
                    #pragma unroll
                    for (int ni = 0; ni < 4; ni++)
                        mma_bf16(acc[mi][ni][0], acc[mi][ni][1], acc[mi][ni][2], acc[mi][ni][3],
                                 af[mi][0], af[mi][1], af[mi][2], af[mi][3],
                                 bf[ni >> 1][(ni & 1) * 2 + 0], bf[ni >> 1][(ni & 1) * 2 + 1]);
            }
        }
    }

    const int p0 = pt * 128 + warp_n * 32 + 2 * (lane & 3);
    #pragma unroll
    for (int mi = 0; mi < 4; mi++) {
        #pragma unroll
        for (int half = 0; half < 2; half++) {
            int m = mt * 128 + warp_m * 64 + mi * 16 + (lane >> 2) + half * 8;
            #pragma unroll
            for (int ni = 0; ni < 4; ni++) {
                float v0 = acc[mi][ni][half * 2 + 0];
                float v1 = acc[mi][ni][half * 2 + 1];
                int p = p0 + ni * 8;
                if (m < 256) {
                    float bias = bv[m];
                    __half2 hv = __floats2half2_rn(v0 + bias, v1 + bias);
                    *(__half2*)&g_v[((size_t)b * 256 + m) * HWS + p] = hv;
                } else if (m < 320) {
                    const bool isq = (m < 288);
                    int c = isq ? (m - 256) : (m - 288);
                    float bias = isq ? bq[c] : bk[c];
                    float f0 = v0 + bias, f1 = v1 + bias;
                    __nv_bfloat16 h0 = __float2bfloat16(f0), h1 = __float2bfloat16(f1);
                    __nv_bfloat16 l0 = __float2bfloat16(f0 - __bfloat162float(h0));
                    __nv_bfloat16 l1 = __float2bfloat16(f1 - __bfloat162float(h1));
                    __nv_bfloat162 hp; hp.x = h0; hp.y = h1;
                    __nv_bfloat162 lp; lp.x = l0; lp.y = l1;
                    size_t off = ((size_t)b * 32 + c) * HWS + p;
                    if (isq) {
                        *(__nv_bfloat162*)&g_qhi[off] = hp;
                        *(__nv_bfloat162*)&g_qlo[off] = lp;
                    } else {
                        *(__nv_bfloat162*)&g_khi[off] = hp;
                        *(__nv_bfloat162*)&g_klo[off] = lp;
                    }
                }
            }
        }
    }
}

// ---------------------------------------------------------------------------
// transpose: 16-bit planes [H][W] -> [W][H]; 64x64 tiles, uint32 vectorized.
// ---------------------------------------------------------------------------
__global__ void transpose_kernel()
{
    __shared__ uint16_t sm[64][70];
    const int plane = blockIdx.z;
    const uint16_t* src;
    uint16_t* dst;
    if (plane < 512) {
        int t = plane >> 7, ch = plane & 127;
        const __nv_bfloat16* s;
        __nv_bfloat16* d;
        switch (t) {
            case 0:  s = g_qhi; d = g_qhiT; break;
            case 1:  s = g_qlo; d = g_qloT; break;
            case 2:  s = g_khi; d = g_khiT; break;
            default: s = g_klo; d = g_kloT; break;
        }
        src = (const uint16_t*)(s + (size_t)ch * HWS);
        dst = (uint16_t*)(d + (size_t)ch * HWS);
    } else {
        int ch = plane - 512;
        src = (const uint16_t*)(g_v + (size_t)ch * HWS);
        dst = (uint16_t*)(g_vT + (size_t)ch * HWS);
    }
    const int ti = blockIdx.y * 64, tj = blockIdx.x * 64;
    const int t = threadIdx.x;
    const int cw = (t & 31) * 2, r0 = t >> 5;
    #pragma unroll
    for (int p = 0; p < 8; p++) {
        int r = r0 + p * 8;
        *(uint32_t*)&sm[r][cw] = *(const uint32_t*)&src[(size_t)(ti + r) * WW + tj + cw];
    }
    __syncthreads();
    const int ch2 = (t & 31) * 2, w0 = t >> 5;
    #pragma unroll
    for (int p = 0; p < 8; p++) {
        int w = w0 + p * 8;
        uint32_t v = (uint32_t)sm[ch2][w] | ((uint32_t)sm[ch2 + 1][w] << 16);
        *(uint32_t*)&dst[(size_t)(tj + w) * HH + ti + ch2] = v;
    }
}

// ---------------------------------------------------------------------------
// Tensor-core criss-cross attention.
// cp.async groups: G1=A0/B0 (energy can start early), G2=V0, G3=A1/B1/V1,
// G4=x epilogue tile (issued after phase 0 into the then-dead V0/A0/B0).
// smem: [0,32K) P | [32K,48K) V0 | [48K,64K) V1 | [64K,72K) A0 | [72K,80K) A1
//       [80K,88K) B0 | [88K,96K) B1 | [96K,97K) ssum
// ---------------------------------------------------------------------------
#define AT_P    0
#define AT_V0   32768
#define AT_V1   49152
#define AT_A0   65536
#define AT_A1   73728
#define AT_B0   81920
#define AT_B1   90112
#define AT_SSUM 98304
#define AT_SMEM (98304 + 1024)

__global__ void __launch_bounds__(256, 2) attn_kernel(
    const float* __restrict__ x, const float* __restrict__ gamma,
    float* __restrict__ out)
{
    char* smem = smem_raw;
    float* ssum = (float*)(smem + AT_SSUM);

    const int i  = blockIdx.x;
    const int bh = blockIdx.y;
    const int b = bh >> 2, h = bh & 3;
    const int tid = threadIdx.x;
    const int wid = tid >> 5, lane = tid & 31;

    const uint32_t smb  = smem_u32(smem);
    const uint32_t sP_u = smb + AT_P;

    const int b_row_in = (lane & 7) + ((lane >> 4) << 3);
    const int b_kseg   = ((lane >> 3) & 1) << 4;
    const int tr_row_a = (lane & 7) + (((lane >> 4) & 1) << 3);
    const int tr_col_a = ((lane >> 3) & 1) << 3;
    const int tr_row_b = (lane & 7) + (((lane >> 3) & 1) << 3);
    const int tr_col_b = ((lane >> 4) & 1) << 3;

    const int em = wid & 1, en = wid >> 1;

    const int qkc0 = (b * 32 + h * 8);
    const int vc0  = (b * 256 + h * 64);
    const int loff = i * 128;

    // zero pad rows 24-31 of A0/A1/B0/B1 (persist across phases)
    #pragma unroll
    for (int z = 0; z < 2; z++) {
        int idx = tid + z * 256;
        int bufsel = idx >> 7;
        int r = 24 + ((idx >> 4) & 7), chunk = idx & 15;
        uint32_t base = (bufsel == 0) ? AT_A0 : (bufsel == 1) ? AT_A1
                       : (bufsel == 2) ? AT_B0 : AT_B1;
        *(uint4*)(smem + base + sw256((uint32_t)(r * 256 + chunk * 16))) =
            make_uint4(0, 0, 0, 0);
    }

    auto issue_AB = [&](int ph) {
        const __nv_bfloat16* Khi = ph ? g_khiT : g_khi;
        const __nv_bfloat16* Klo = ph ? g_kloT : g_klo;
        const __nv_bfloat16* Qhi = ph ? g_qhiT : g_qhi;
        const __nv_bfloat16* Qlo = ph ? g_qloT : g_qlo;
        const uint32_t aU = smb + (ph ? AT_A1 : AT_A0);
        const uint32_t bU = smb + (ph ? AT_B1 : AT_B0);
        #pragma unroll
        for (int it = 0; it < 3; it++) {
            int idx = tid + it * 256;
            int rr2 = idx >> 4, chunk = idx & 15;
            int tile = rr2 >= 24;
            int r = tile ? (rr2 - 24) : rr2;
            int c = r & 7;
            const __nv_bfloat16* src;
            if (!tile) src = (r < 16) ? Khi : Klo;
            else       src = (r >= 8 && r < 16) ? Qlo : Qhi;
            const char* gsrc = (const char*)(src + (size_t)(qkc0 + c) * HWS + loff) + chunk * 16;
            uint32_t dst = (tile ? bU : aU) + sw256((uint32_t)(r * 256 + chunk * 16));
            CP_ASYNC16(dst, gsrc);
        }
    };
    auto issue_V = [&](int ph) {
        const __half* Vp = ph ? g_vT : g_v;
        const uint32_t vU = smb + (ph ? AT_V1 : AT_V0);
        #pragma unroll
        for (int it = 0; it < 4; it++) {
            int idx = tid + it * 256;
            int c = idx >> 4, chunk = idx & 15;
            const char* gsrc = (const char*)(Vp + (size_t)(vc0 + c) * HWS + loff) + chunk * 16;
            CP_ASYNC16(vU + sw256((uint32_t)(c * 256 + chunk * 16)), gsrc);
        }
    };

    issue_AB(0); CP_COMMIT();                 // G1
    issue_V(0);  CP_COMMIT();                 // G2
    issue_AB(1); issue_V(1); CP_COMMIT();     // G3

    float acc[8][4];
    #pragma unroll
    for (int ni = 0; ni < 8; ni++)
        #pragma unroll
        for (int k = 0; k < 4; k++) acc[ni][k] = 0.0f;

    for (int phase = 0; phase < 2; phase++) {
        const uint32_t sA_u = smb + (phase ? AT_A1 : AT_A0);
        const uint32_t sB_u = smb + (phase ? AT_B1 : AT_B0);
        const uint32_t sV_u = smb + (phase ? AT_V1 : AT_V0);
        if (phase == 0) { CP_WAIT2(); } else { CP_WAIT1(); }
        __syncthreads();

        // ---- energy mma: A,B via trans-ldmatrix from [c'][g] tiles ----
        float ef[4][4][4];
        #pragma unroll
        for (int mi = 0; mi < 4; mi++)
            #pragma unroll
            for (int ni = 0; ni < 4; ni++)
                #pragma unroll
                for (int k = 0; k < 4; k++) ef[mi][ni][k] = 0.0f;
        #pragma unroll
        for (int ks = 0; ks < 2; ks++) {
            uint32_t af[4][4];
            #pragma unroll
            for (int mi = 0; mi < 4; mi++) {
                int row = ks * 16 + tr_row_a;
                int col = em * 64 + mi * 16 + tr_col_a;
                ldmatrix_x4_trans(af[mi][0], af[mi][1], af[mi][2], af[mi][3],
                                  sA_u + sw256((uint32_t)(row * 256 + col * 2)));
            }
            uint32_t bfr[2][4];
            #pragma unroll
            for (int n16 = 0; n16 < 2; n16++) {
                int row = ks * 16 + tr_row_b;
                int col = en * 32 + n16 * 16 + tr_col_b;
                ldmatrix_x4_trans(bfr[n16][0], bfr[n16][1], bfr[n16][2], bfr[n16][3],
                                  sB_u + sw256((uint32_t)(row * 256 + col * 2)));
            }
            #pragma unroll
            for (int mi = 0; mi < 4; mi++)
                #pragma unroll
                for (int ni = 0; ni < 4; ni++)
                    mma_bf16(ef[mi][ni][0], ef[mi][ni][1], ef[mi][ni][2], ef[mi][ni][3],
                             af[mi][0], af[mi][1], af[mi][2], af[mi][3],
                             bfr[ni >> 1][(ni & 1) * 2 + 0], bfr[ni >> 1][(ni & 1) * 2 + 1]);
        }

        // ---- exp in registers + per-j column sums ----
        float psum[4][2];
        #pragma unroll
        for (int ni = 0; ni < 4; ni++) { psum[ni][0] = 0.0f; psum[ni][1] = 0.0f; }
        #pragma unroll
        for (int mi = 0; mi < 4; mi++)
            #pragma unroll
            for (int ni = 0; ni < 4; ni++) {
                ef[mi][ni][0] = __expf(ef[mi][ni][0]);
                ef[mi][ni][1] = __expf(ef[mi][ni][1]);
                ef[mi][ni][2] = __expf(ef[mi][ni][2]);
                ef[mi][ni][3] = __expf(ef[mi][ni][3]);
                psum[ni][0] += ef[mi][ni][0] + ef[mi][ni][2];
                psum[ni][1] += ef[mi][ni][1] + ef[mi][ni][3];
            }
        #pragma unroll
        for (int ni = 0; ni < 4; ni++) {
            #pragma unroll
            for (int d = 4; d <= 16; d <<= 1) {
                psum[ni][0] += __shfl_xor_sync(0xffffffffu, psum[ni][0], d);
                psum[ni][1] += __shfl_xor_sync(0xffffffffu, psum[ni][1], d);
            }
        }
        if ((lane >> 2) == 0) {
            #pragma unroll
            for (int ni = 0; ni < 4; ni++) {
                int j0 = en * 32 + ni * 8 + (lane & 3) * 2;
                *(float2*)&ssum[em * 128 + j0] = make_float2(psum[ni][0], psum[ni][1]);
            }
        }
        __syncthreads();

        // ---- normalize + store P fp16 [g][j] ----
        #pragma unroll
        for (int ni = 0; ni < 4; ni++) {
            int j0 = en * 32 + ni * 8 + (lane & 3) * 2;
            float2 sa = *(float2*)&ssum[j0];
            float2 sb = *(float2*)&ssum[128 + j0];
            float is0 = 1.0f / (sa.x + sb.x);
            float is1 = 1.0f / (sa.y + sb.y);
            #pragma unroll
            for (int mi = 0; mi < 4; mi++) {
                int g0 = em * 64 + mi * 16 + (lane >> 2);
                __half2 p0 = __floats2half2_rn(ef[mi][ni][0] * is0, ef[mi][ni][1] * is1);
                __half2 p1 = __floats2half2_rn(ef[mi][ni][2] * is0, ef[mi][ni][3] * is1);
                *(uint32_t*)(smem + AT_P + sw256((uint32_t)(g0 * 256 + j0 * 2)))       = *(uint32_t*)&p0;
                *(uint32_t*)(smem + AT_P + sw256((uint32_t)((g0 + 8) * 256 + j0 * 2))) = *(uint32_t*)&p1;
            }
        }
        if (phase == 0) CP_WAIT1();   // V0 arrived (G2)
        __syncthreads();

        // ---- O mma: A = P (m=j, k=g, trans), B = V (n=c, k=g) ----
        {
            #pragma unroll
            for (int ks = 0; ks < 8; ks++) {
                uint32_t af[4];
                {
                    int row = ks * 16 + tr_row_a;
                    int col = wid * 16 + tr_col_a;
                    ldmatrix_x4_trans(af[0], af[1], af[2], af[3],
                                      sP_u + sw256((uint32_t)(row * 256 + col * 2)));
                }
                uint32_t bfr[4][4];
                #pragma unroll
                for (int n16 = 0; n16 < 4; n16++) {
                    int row = n16 * 16 + b_row_in;
                    ldmatrix_x4(bfr[n16][0], bfr[n16][1], bfr[n16][2], bfr[n16][3],
                                sV_u + sw256((uint32_t)(row * 256 + ks * 32) + (uint32_t)b_kseg));
                }
                #pragma unroll
                for (int n16 = 0; n16 < 4; n16++)
                    #pragma unroll
                    for (int sub = 0; sub < 2; sub++)
                        mma_f16(acc[n16 * 2 + sub][0], acc[n16 * 2 + sub][1],
                                acc[n16 * 2 + sub][2], acc[n16 * 2 + sub][3],
                                af[0], af[1], af[2], af[3],
                                bfr[n16][sub * 2 + 0], bfr[n16][sub * 2 + 1]);
            }
        }
        if (phase == 1) CP_WAIT0();   // x tile arrived (G4)
        __syncthreads();

        if (phase == 0) {
            // prefetch epilogue x tile (64ch x 128j fp32) into dead V0/A0/B0
            #pragma unroll
            for (int it = 0; it < 8; it++) {
                int idx = tid + it * 256;
                int c = idx >> 5, jseg = idx & 31;
                const char* gsrc = (const char*)(x + ((size_t)(vc0 + c) * HH + i) * WW)
                                   + jseg * 16;
                uint32_t dstoff = (c < 32) ? (uint32_t)(AT_V0 + c * 512)
                                : (c < 48) ? (uint32_t)(AT_A0 + (c - 32) * 512)
                                           : (uint32_t)(AT_B0 + (c - 48) * 512);
                CP_ASYNC16(smb + dstoff + jseg * 16, gsrc);
            }
            CP_COMMIT();              // G4
        }
    }

    // ---- epilogue: x from smem staging ----
    const float gm = gamma[0];
    const int jb = wid * 16 + (lane >> 2);
    #pragma unroll
    for (int ni = 0; ni < 8; ni++) {
        int c0 = ni * 8 + (lane & 3) * 2;
        uint32_t xbase = (ni < 4) ? (uint32_t)(AT_V0 + c0 * 512)
                      : (ni < 6) ? (uint32_t)(AT_A0 + (c0 - 32) * 512)
                                 : (uint32_t)(AT_B0 + (c0 - 48) * 512);
        #pragma unroll
        for (int hf = 0; hf < 2; hf++) {
            int j = jb + hf * 8;
            size_t off0 = (((size_t)vc0 + c0) * HH + i) * WW + j;
            size_t off1 = off0 + HWS;
            float x0 = *(const float*)(smem + xbase + j * 4);
            float x1 = *(const float*)(smem + xbase + 512 + j * 4);
            out[off0] = gm * acc[ni][hf * 2 + 0] + x0;
            out[off1] = gm * acc[ni][hf * 2 + 1] + x1;
        }
    }
}

// ---------------------------------------------------------------------------
extern "C" void kernel_launch(void* const* d_in, const int* in_sizes, int n_in,
                              void* d_out, int out_size)
{
    const float* x     = (const float*)d_in[0];
    const float* Wq    = (const float*)d_in[1];
    const float* bq    = (const float*)d_in[2];
    const float* Wk    = (const float*)d_in[3];
    const float* bk    = (const float*)d_in[4];
    const float* Wv    = (const float*)d_in[5];
    const float* bv    = (const float*)d_in[6];
    const float* gamma = (const float*)d_in[7];
    float* out = (float*)d_out;

    cudaFuncSetAttribute(attn_kernel, cudaFuncAttributeMaxDynamicSharedMemorySize,
                         AT_SMEM);
    cudaFuncSetAttribute(proj_mma_kernel, cudaFuncAttributeMaxDynamicSharedMemorySize,
                         98304);

    prep_w_kernel<<<384, 256>>>(Wq, Wk, Wv);
    prep_x_kernel<<<dim3(256, 4, NB), 256>>>(x);
    proj_mma_kernel<<<dim3(128, 3, NB), 256, 98304>>>(bq, bk, bv);
    transpose_kernel<<<dim3(2, 2, 1536), 256>>>();
    attn_kernel<<<dim3(HH, NB * 4), 256, AT_SMEM>>>(x, gamma, out);
}

// round 13
// speedup vs baseline: 1.0361x; 1.0361x over previous
#include <cuda_runtime.h>
#include <cuda_bf16.h>
#include <cuda_fp16.h>
#include <cstdint>

#define HH 128
#define WW 128
#define HWS 16384
#define NB 4
#define KP 512   // split-K storage: [hi(256) | lo(256)]; 12 virtual chunks at GEMM

// ---------------- scratch (device globals; allocation-free rule) ------------
__device__ __align__(16) __nv_bfloat16 g_qhi[(size_t)NB * 32 * HWS];
__device__ __align__(16) __nv_bfloat16 g_qlo[(size_t)NB * 32 * HWS];
__device__ __align__(16) __nv_bfloat16 g_khi[(size_t)NB * 32 * HWS];
__device__ __align__(16) __nv_bfloat16 g_klo[(size_t)NB * 32 * HWS];
__device__ __align__(16) __nv_bfloat16 g_qhiT[(size_t)NB * 32 * HWS];
__device__ __align__(16) __nv_bfloat16 g_qloT[(size_t)NB * 32 * HWS];
__device__ __align__(16) __nv_bfloat16 g_khiT[(size_t)NB * 32 * HWS];
__device__ __align__(16) __nv_bfloat16 g_kloT[(size_t)NB * 32 * HWS];
__device__ __align__(16) __half g_v [(size_t)NB * 256 * HWS];
__device__ __align__(16) __half g_vT[(size_t)NB * 256 * HWS];
__device__ __align__(16) __nv_bfloat16 g_wsplit[(size_t)384 * KP];       // [m][hi|lo]
__device__ __align__(16) __nv_bfloat16 g_xt[(size_t)NB * HWS * KP];      // [b][p][hi|lo]

// single TU-wide dynamic smem symbol (char; cast per-kernel)
extern __shared__ __align__(1024) char smem_raw[];

static __device__ __forceinline__ uint32_t sw128(uint32_t off) {
    return off ^ ((off >> 3) & 0x70);
}
static __device__ __forceinline__ uint32_t sw256(uint32_t off) {
    return off ^ (((off >> 8) & 7) << 4);
}
__device__ __forceinline__ uint32_t smem_u32(const void* p) {
    uint32_t a;
    asm("{ .reg .u64 t; cvta.to.shared.u64 t, %1; cvt.u32.u64 %0, t; }"
        : "=r"(a) : "l"(p));
    return a;
}
__device__ __forceinline__ void ldmatrix_x4(uint32_t& r0, uint32_t& r1,
                                            uint32_t& r2, uint32_t& r3, uint32_t addr) {
    asm volatile("ldmatrix.sync.aligned.m8n8.x4.shared.b16 {%0,%1,%2,%3}, [%4];"
                 : "=r"(r0), "=r"(r1), "=r"(r2), "=r"(r3) : "r"(addr));
}
__device__ __forceinline__ void ldmatrix_x4_trans(uint32_t& r0, uint32_t& r1,
                                                  uint32_t& r2, uint32_t& r3, uint32_t addr) {
    asm volatile("ldmatrix.sync.aligned.m8n8.x4.trans.shared.b16 {%0,%1,%2,%3}, [%4];"
                 : "=r"(r0), "=r"(r1), "=r"(r2), "=r"(r3) : "r"(addr));
}
__device__ __forceinline__ void mma_bf16(float& d0, float& d1, float& d2, float& d3,
                                         uint32_t a0, uint32_t a1, uint32_t a2, uint32_t a3,
                                         uint32_t b0, uint32_t b1) {
    asm volatile("mma.sync.aligned.m16n8k16.row.col.f32.bf16.bf16.f32 "
                 "{%0,%1,%2,%3}, {%4,%5,%6,%7}, {%8,%9}, {%0,%1,%2,%3};"
                 : "+f"(d0), "+f"(d1), "+f"(d2), "+f"(d3)
                 : "r"(a0), "r"(a1), "r"(a2), "r"(a3), "r"(b0), "r"(b1));
}
__device__ __forceinline__ void mma_f16(float& d0, float& d1, float& d2, float& d3,
                                        uint32_t a0, uint32_t a1, uint32_t a2, uint32_t a3,
                                        uint32_t b0, uint32_t b1) {
    asm volatile("mma.sync.aligned.m16n8k16.row.col.f32.f16.f16.f32 "
                 "{%0,%1,%2,%3}, {%4,%5,%6,%7}, {%8,%9}, {%0,%1,%2,%3};"
                 : "+f"(d0), "+f"(d1), "+f"(d2), "+f"(d3)
                 : "r"(a0), "r"(a1), "r"(a2), "r"(a3), "r"(b0), "r"(b1));
}
#define CP_ASYNC16(dst, src) \
    asm volatile("cp.async.cg.shared.global [%0], [%1], 16;" :: "r"(dst), "l"(src))
#define CP_COMMIT() asm volatile("cp.async.commit_group;" ::: "memory")
#define CP_WAIT2()  asm volatile("cp.async.wait_group 2;" ::: "memory")
#define CP_WAIT1()  asm volatile("cp.async.wait_group 1;" ::: "memory")
#define CP_WAIT0()  asm volatile("cp.async.wait_group 0;" ::: "memory")

// ---------------------------------------------------------------------------
// prep_w: W' bf16 [384][512]; rows 0-255 Wv, 256-287 Wq, 288-319 Wk, 320-383 0
// ---------------------------------------------------------------------------
__global__ void prep_w_kernel(const float* __restrict__ Wq, const float* __restrict__ Wk,
                              const float* __restrict__ Wv)
{
    const int m = blockIdx.x;
    const int c = threadIdx.x;
    float w = 0.0f;
    if (m < 256)      w = Wv[m * 256 + c];
    else if (m < 288) w = Wq[(m - 256) * 256 + c];
    else if (m < 320) w = Wk[(m - 288) * 256 + c];
    __nv_bfloat16 hi = __float2bfloat16(w);
    __nv_bfloat16 lo = __float2bfloat16(w - __bfloat162float(hi));
    g_wsplit[(size_t)m * KP + c]       = hi;
    g_wsplit[(size_t)m * KP + 256 + c] = lo;
}

// ---------------------------------------------------------------------------
// prep_x: XT' bf16 [b][p][512]: cols [0:256)=hi, [256:512)=lo
// ---------------------------------------------------------------------------
__global__ void prep_x_kernel(const float* __restrict__ x)
{
    __shared__ float sm[64][65];
    const int b = blockIdx.z, ct = blockIdx.y, pt = blockIdx.x;
    const int c0 = ct * 64, p0 = pt * 64;
    const int t = threadIdx.x;
    const int pj = t & 63, ci0 = t >> 6;
    const float* xb = x + ((size_t)b * 256 + c0) * HWS + p0;
    #pragma unroll
    for (int i = 0; i < 16; i++) {
        int ci = ci0 + i * 4;
        sm[ci][pj] = xb[(size_t)ci * HWS + pj];
    }
    __syncthreads();
    const int cp = t & 31, pl = t >> 5;
    #pragma unroll
    for (int i = 0; i < 8; i++) {
        int p = pl + i * 8;
        float f0 = sm[2 * cp][p], f1 = sm[2 * cp + 1][p];
        __nv_bfloat16 h0 = __float2bfloat16(f0), h1 = __float2bfloat16(f1);
        __nv_bfloat16 l0 = __float2bfloat16(f0 - __bfloat162float(h0));
        __nv_bfloat16 l1 = __float2bfloat16(f1 - __bfloat162float(h1));
        __nv_bfloat162 hp; hp.x = h0; hp.y = h1;
        __nv_bfloat162 lp; lp.x = l0; lp.y = l1;
        __nv_bfloat16* row = g_xt + ((size_t)b * HWS + p0 + p) * KP;
        *(__nv_bfloat162*)(row + c0 + 2 * cp)       = hp;
        *(__nv_bfloat162*)(row + 256 + c0 + 2 * cp) = lp;
    }
}

// ---------------------------------------------------------------------------
// proj_mma: 2-stage cp.async double-buffered bf16 mma GEMM (R10 known-good:
// 64KB smem -> 3 blocks/SM; cross-block overlap does the latency hiding).
// ---------------------------------------------------------------------------
__constant__ int ACH[12] = {0, 1, 2, 3, 0, 1, 2, 3, 4, 5, 6, 7};
__constant__ int BCH[12] = {0, 1, 2, 3, 4, 5, 6, 7, 0, 1, 2, 3};

__global__ void __launch_bounds__(256) proj_mma_kernel(
    const float* __restrict__ bq, const float* __restrict__ bk,
    const float* __restrict__ bv)
{
    char* smem = smem_raw;
    const uint32_t smem_base = smem_u32(smem);
    const int tid = threadIdx.x;
    const int wid = tid >> 5, lane = tid & 31;
    const int warp_m = wid & 1;
    const int warp_n = wid >> 1;
    const int pt = blockIdx.x, mt = blockIdx.y, b = blockIdx.z;
    const bool mma_active = (mt < 2) || (warp_m == 0);

    const char* Abase = (const char*)(g_wsplit + (size_t)mt * 128 * KP);
    const char* Bbase = (const char*)(g_xt + ((size_t)b * HWS + pt * 128) * KP);

    float acc[4][4][4];
    #pragma unroll
    for (int i = 0; i < 4; i++)
        #pragma unroll
        for (int j = 0; j < 4; j++)
            #pragma unroll
            for (int k = 0; k < 4; k++) acc[i][j][k] = 0.0f;

    const int a_row_in = lane & 15;
    const int a_kseg   = (lane >> 4) << 4;
    const int b_row_in = (lane & 7) + ((lane >> 4) << 3);
    const int b_kseg   = ((lane >> 3) & 1) << 4;

    const int ld_row = tid >> 3, ld_seg = tid & 7;

    auto issue = [&](int ch, int st) {
        const size_t a0b = (size_t)ACH[ch] * 128;
        const size_t b0b = (size_t)BCH[ch] * 128;
        const uint32_t sb = smem_base + st * 32768;
        #pragma unroll
        for (int r = 0; r < 4; r++) {
            int row = ld_row + r * 32;
            uint32_t so = sw128((uint32_t)(row * 128 + ld_seg * 16));
            CP_ASYNC16(sb + so,         Abase + (size_t)row * (KP * 2) + a0b + ld_seg * 16);
            CP_ASYNC16(sb + 16384 + so, Bbase + (size_t)row * (KP * 2) + b0b + ld_seg * 16);
        }
    };

    issue(0, 0);
    CP_COMMIT();

    for (int ch = 0; ch < 12; ch++) {
        const int st = ch & 1;
        if (ch + 1 < 12) issue(ch + 1, st ^ 1);
        CP_COMMIT();
        CP_WAIT1();
        __syncthreads();

        if (mma_active) {
            const uint32_t sA_u = smem_base + st * 32768;
            const uint32_t sB_u = sA_u + 16384;
            #pragma unroll
            for (int kk = 0; kk < 4; kk++) {
                uint32_t af[4][4];
                #pragma unroll
                for (int mi = 0; mi < 4; mi++) {
                    int row = warp_m * 64 + mi * 16 + a_row_in;
                    ldmatrix_x4(af[mi][0], af[mi][1], af[mi][2], af[mi][3],
                                sA_u + sw128((uint32_t)(row * 128 + kk * 32 + a_kseg)));
                }
                uint32_t bf[2][4];
                #pragma unroll
                for (int ni16 = 0; ni16 < 2; ni16++) {
                    int row = warp_n * 32 + ni16 * 16 + b_row_in;
                    ldmatrix_x4(bf[ni16][0], bf[ni16][1], bf[ni16][2], bf[ni16][3],
                                sB_u + sw128((uint32_t)(row * 128 + kk * 32 + b_kseg)));
                }
                #pragma unroll
                for (int mi = 0; mi < 4; mi++)
                    #pragma unroll
                    for (int ni = 0; ni < 4; ni++)
                        mma_bf16(acc[mi][ni][0], acc[mi][ni][1], acc[mi][ni][2], acc[mi][ni][3],
                                 af[mi][0], af[mi][1], af[mi][2], af[mi][3],
                                 bf[ni >> 1][(ni & 1) * 2 + 0], bf[ni >> 1][(ni & 1) * 2 + 1]);
            }
        }
        __syncthreads();
    }

    const int p0 = pt * 128 + warp_n * 32 + 2 * (lane & 3);
    #pragma unroll
    for (int mi = 0; mi < 4; mi++) {
        #pragma unroll
        for (int half = 0; half < 2; half++) {
            int m = mt * 128 + warp_m * 64 + mi * 16 + (lane >> 2) + half * 8;
            #pragma unroll
            for (int ni = 0; ni < 4; ni++) {
                float v0 = acc[mi][ni][half * 2 + 0];
                float v1 = acc[mi][ni][half * 2 + 1];
                int p = p0 + ni * 8;
                if (m < 256) {
                    float bias = bv[m];
                    __half2 hv = __floats2half2_rn(v0 + bias, v1 + bias);
                    *(__half2*)&g_v[((size_t)b * 256 + m) * HWS + p] = hv;
                } else if (m < 320) {
                    const bool isq = (m < 288);
                    int c = isq ? (m - 256) : (m - 288);
                    float bias = isq ? bq[c] : bk[c];
                    float f0 = v0 + bias, f1 = v1 + bias;
                    __nv_bfloat16 h0 = __float2bfloat16(f0), h1 = __float2bfloat16(f1);
                    __nv_bfloat16 l0 = __float2bfloat16(f0 - __bfloat162float(h0));
                    __nv_bfloat16 l1 = __float2bfloat16(f1 - __bfloat162float(h1));
                    __nv_bfloat162 hp; hp.x = h0; hp.y = h1;
                    __nv_bfloat162 lp; lp.x = l0; lp.y = l1;
                    size_t off = ((size_t)b * 32 + c) * HWS + p;
                    if (isq) {
                        *(__nv_bfloat162*)&g_qhi[off] = hp;
                        *(__nv_bfloat162*)&g_qlo[off] = lp;
                    } else {
                        *(__nv_bfloat162*)&g_khi[off] = hp;
                        *(__nv_bfloat162*)&g_klo[off] = lp;
                    }
                }
            }
        }
    }
}

// ---------------------------------------------------------------------------
// transpose: 16-bit planes [H][W] -> [W][H]; 64x64 tiles, uint32 vectorized.
// ---------------------------------------------------------------------------
__global__ void transpose_kernel()
{
    __shared__ uint16_t sm[64][70];
    const int plane = blockIdx.z;
    const uint16_t* src;
    uint16_t* dst;
    if (plane < 512) {
        int t = plane >> 7, ch = plane & 127;
        const __nv_bfloat16* s;
        __nv_bfloat16* d;
        switch (t) {
            case 0:  s = g_qhi; d = g_qhiT; break;
            case 1:  s = g_qlo; d = g_qloT; break;
            case 2:  s = g_khi; d = g_khiT; break;
            default: s = g_klo; d = g_kloT; break;
        }
        src = (const uint16_t*)(s + (size_t)ch * HWS);
        dst = (uint16_t*)(d + (size_t)ch * HWS);
    } else {
        int ch = plane - 512;
        src = (const uint16_t*)(g_v + (size_t)ch * HWS);
        dst = (uint16_t*)(g_vT + (size_t)ch * HWS);
    }
    const int ti = blockIdx.y * 64, tj = blockIdx.x * 64;
    const int t = threadIdx.x;
    const int cw = (t & 31) * 2, r0 = t >> 5;
    #pragma unroll
    for (int p = 0; p < 8; p++) {
        int r = r0 + p * 8;
        *(uint32_t*)&sm[r][cw] = *(const uint32_t*)&src[(size_t)(ti + r) * WW + tj + cw];
    }
    __syncthreads();
    const int ch2 = (t & 31) * 2, w0 = t >> 5;
    #pragma unroll
    for (int p = 0; p < 8; p++) {
        int w = w0 + p * 8;
        uint32_t v = (uint32_t)sm[ch2][w] | ((uint32_t)sm[ch2 + 1][w] << 16);
        *(uint32_t*)&dst[(size_t)(tj + w) * HH + ti + ch2] = v;
    }
}

// ---------------------------------------------------------------------------
// Tensor-core criss-cross attention (R12 version — kept).
// cp.async groups: G1=A0/B0, G2=V0, G3=A1/B1/V1, G4=x epilogue tile.
// smem: [0,32K) P | [32K,48K) V0 | [48K,64K) V1 | [64K,72K) A0 | [72K,80K) A1
//       [80K,88K) B0 | [88K,96K) B1 | [96K,97K) ssum
// ---------------------------------------------------------------------------
#define AT_P    0
#define AT_V0   32768
#define AT_V1   49152
#define AT_A0   65536
#define AT_A1   73728
#define AT_B0   81920
#define AT_B1   90112
#define AT_SSUM 98304
#define AT_SMEM (98304 + 1024)

__global__ void __launch_bounds__(256, 2) attn_kernel(
    const float* __restrict__ x, const float* __restrict__ gamma,
    float* __restrict__ out)
{
    char* smem = smem_raw;
    float* ssum = (float*)(smem + AT_SSUM);

    const int i  = blockIdx.x;
    const int bh = blockIdx.y;
    const int b = bh >> 2, h = bh & 3;
    const int tid = threadIdx.x;
    const int wid = tid >> 5, lane = tid & 31;

    const uint32_t smb  = smem_u32(smem);
    const uint32_t sP_u = smb + AT_P;

    const int b_row_in = (lane & 7) + ((lane >> 4) << 3);
    const int b_kseg   = ((lane >> 3) & 1) << 4;
    const int tr_row_a = (lane & 7) + (((lane >> 4) & 1) << 3);
    const int tr_col_a = ((lane >> 3) & 1) << 3;
    const int tr_row_b = (lane & 7) + (((lane >> 3) & 1) << 3);
    const int tr_col_b = ((lane >> 4) & 1) << 3;

    const int em = wid & 1, en = wid >> 1;

    const int qkc0 = (b * 32 + h * 8);
    const int vc0  = (b * 256 + h * 64);
    const int loff = i * 128;

    // zero pad rows 24-31 of A0/A1/B0/B1 (persist across phases)
    #pragma unroll
    for (int z = 0; z < 2; z++) {
        int idx = tid + z * 256;
        int bufsel = idx >> 7;
        int r = 24 + ((idx >> 4) & 7), chunk = idx & 15;
        uint32_t base = (bufsel == 0) ? AT_A0 : (bufsel == 1) ? AT_A1
                       : (bufsel == 2) ? AT_B0 : AT_B1;
        *(uint4*)(smem + base + sw256((uint32_t)(r * 256 + chunk * 16))) =
            make_uint4(0, 0, 0, 0);
    }

    auto issue_AB = [&](int ph) {
        const __nv_bfloat16* Khi = ph ? g_khiT : g_khi;
        const __nv_bfloat16* Klo = ph ? g_kloT : g_klo;
        const __nv_bfloat16* Qhi = ph ? g_qhiT : g_qhi;
        const __nv_bfloat16* Qlo = ph ? g_qloT : g_qlo;
        const uint32_t aU = smb + (ph ? AT_A1 : AT_A0);
        const uint32_t bU = smb + (ph ? AT_B1 : AT_B0);
        #pragma unroll
        for (int it = 0; it < 3; it++) {
            int idx = tid + it * 256;
            int rr2 = idx >> 4, chunk = idx & 15;
            int tile = rr2 >= 24;
            int r = tile ? (rr2 - 24) : rr2;
            int c = r & 7;
            const __nv_bfloat16* src;
            if (!tile) src = (r < 16) ? Khi : Klo;
            else       src = (r >= 8 && r < 16) ? Qlo : Qhi;
            const char* gsrc = (const char*)(src + (size_t)(qkc0 + c) * HWS + loff) + chunk * 16;
            uint32_t dst = (tile ? bU : aU) + sw256((uint32_t)(r * 256 + chunk * 16));
            CP_ASYNC16(dst, gsrc);
        }
    };
    auto issue_V = [&](int ph) {
        const __half* Vp = ph ? g_vT : g_v;
        const uint32_t vU = smb + (ph ? AT_V1 : AT_V0);
        #pragma unroll
        for (int it = 0; it < 4; it++) {
            int idx = tid + it * 256;
            int c = idx >> 4, chunk = idx & 15;
            const char* gsrc = (const char*)(Vp + (size_t)(vc0 + c) * HWS + loff) + chunk * 16;
            CP_ASYNC16(vU + sw256((uint32_t)(c * 256 + chunk * 16)), gsrc);
        }
    };

    issue_AB(0); CP_COMMIT();                 // G1
    issue_V(0);  CP_COMMIT();                 // G2
    issue_AB(1); issue_V(1); CP_COMMIT();     // G3

    float acc[8][4];
    #pragma unroll
    for (int ni = 0; ni < 8; ni++)
        #pragma unroll
        for (int k = 0; k < 4; k++) acc[ni][k] = 0.0f;

    for (int phase = 0; phase < 2; phase++) {
        const uint32_t sA_u = smb + (phase ? AT_A1 : AT_A0);
        const uint32_t sB_u = smb + (phase ? AT_B1 : AT_B0);
        const uint32_t sV_u = smb + (phase ? AT_V1 : AT_V0);
        if (phase == 0) { CP_WAIT2(); } else { CP_WAIT1(); }
        __syncthreads();

        // ---- energy mma: A,B via trans-ldmatrix from [c'][g] tiles ----
        float ef[4][4][4];
        #pragma unroll
        for (int mi = 0; mi < 4; mi++)
            #pragma unroll
            for (int ni = 0; ni < 4; ni++)
                #pragma unroll
                for (int k = 0; k < 4; k++) ef[mi][ni][k] = 0.0f;
        #pragma unroll
        for (int ks = 0; ks < 2; ks++) {
            uint32_t af[4][4];
            #pragma unroll
            for (int mi = 0; mi < 4; mi++) {
                int row = ks * 16 + tr_row_a;
                int col = em * 64 + mi * 16 + tr_col_a;
                ldmatrix_x4_trans(af[mi][0], af[mi][1], af[mi][2], af[mi][3],
                                  sA_u + sw256((uint32_t)(row * 256 + col * 2)));
            }
            uint32_t bfr[2][4];
            #pragma unroll
            for (int n16 = 0; n16 < 2; n16++) {
                int row = ks * 16 + tr_row_b;
                int col = en * 32 + n16 * 16 + tr_col_b;
                ldmatrix_x4_trans(bfr[n16][0], bfr[n16][1], bfr[n16][2], bfr[n16][3],
                                  sB_u + sw256((uint32_t)(row * 256 + col * 2)));
            }
            #pragma unroll
            for (int mi = 0; mi < 4; mi++)
                #pragma unroll
                for (int ni = 0; ni < 4; ni++)
                    mma_bf16(ef[mi][ni][0], ef[mi][ni][1], ef[mi][ni][2], ef[mi][ni][3],
                             af[mi][0], af[mi][1], af[mi][2], af[mi][3],
                             bfr[ni >> 1][(ni & 1) * 2 + 0], bfr[ni >> 1][(ni & 1) * 2 + 1]);
        }

        // ---- exp in registers + per-j column sums ----
        float psum[4][2];
        #pragma unroll
        for (int ni = 0; ni < 4; ni++) { psum[ni][0] = 0.0f; psum[ni][1] = 0.0f; }
        #pragma unroll
        for (int mi = 0; mi < 4; mi++)
            #pragma unroll
            for (int ni = 0; ni < 4; ni++) {
                ef[mi][ni][0] = __expf(ef[mi][ni][0]);
                ef[mi][ni][1] = __expf(ef[mi][ni][1]);
                ef[mi][ni][2] = __expf(ef[mi][ni][2]);
                ef[mi][ni][3] = __expf(ef[mi][ni][3]);
                psum[ni][0] += ef[mi][ni][0] + ef[mi][ni][2];
                psum[ni][1] += ef[mi][ni][1] + ef[mi][ni][3];
            }
        #pragma unroll
        for (int ni = 0; ni < 4; ni++) {
            #pragma unroll
            for (int d = 4; d <= 16; d <<= 1) {
                psum[ni][0] += __shfl_xor_sync(0xffffffffu, psum[ni][0], d);
                psum[ni][1] += __shfl_xor_sync(0xffffffffu, psum[ni][1], d);
            }
        }
        if ((lane >> 2) == 0) {
            #pragma unroll
            for (int ni = 0; ni < 4; ni++) {
                int j0 = en * 32 + ni * 8 + (lane & 3) * 2;
                *(float2*)&ssum[em * 128 + j0] = make_float2(psum[ni][0], psum[ni][1]);
            }
        }
        __syncthreads();

        // ---- normalize + store P fp16 [g][j] ----
        #pragma unroll
        for (int ni = 0; ni < 4; ni++) {
            int j0 = en * 32 + ni * 8 + (lane & 3) * 2;
            float2 sa = *(float2*)&ssum[j0];
            float2 sb = *(float2*)&ssum[128 + j0];
            float is0 = 1.0f / (sa.x + sb.x);
            float is1 = 1.0f / (sa.y + sb.y);
            #pragma unroll
            for (int mi = 0; mi < 4; mi++) {
                int g0 = em * 64 + mi * 16 + (lane >> 2);
                __half2 p0 = __floats2half2_rn(ef[mi][ni][0] * is0, ef[mi][ni][1] * is1);
                __half2 p1 = __floats2half2_rn(ef[mi][ni][2] * is0, ef[mi][ni][3] * is1);
                *(uint32_t*)(smem + AT_P + sw256((uint32_t)(g0 * 256 + j0 * 2)))       = *(uint32_t*)&p0;
                *(uint32_t*)(smem + AT_P + sw256((uint32_t)((g0 + 8) * 256 + j0 * 2))) = *(uint32_t*)&p1;
            }
        }
        if (phase == 0) CP_WAIT1();   // V0 arrived (G2)
        __syncthreads();

        // ---- O mma: A = P (m=j, k=g, trans), B = V (n=c, k=g) ----
        {
            #pragma unroll
            for (int ks = 0; ks < 8; ks++) {
                uint32_t af[4];
                {
                    int row = ks * 16 + tr_row_a;
                    int col = wid * 16 + tr_col_a;
                    ldmatrix_x4_trans(af[0], af[1], af[2], af[3],
                                      sP_u + sw256((uint32_t)(row * 256 + col * 2)));
                }
                uint32_t bfr[4][4];
                #pragma unroll
                for (int n16 = 0; n16 < 4; n16++) {
                    int row = n16 * 16 + b_row_in;
                    ldmatrix_x4(bfr[n16][0], bfr[n16][1], bfr[n16][2], bfr[n16][3],
                                sV_u + sw256((uint32_t)(row * 256 + ks * 32) + (uint32_t)b_kseg));
                }
                #pragma unroll
                for (int n16 = 0; n16 < 4; n16++)
                    #pragma unroll
                    for (int sub = 0; sub < 2; sub++)
                        mma_f16(acc[n16 * 2 + sub][0], acc[n16 * 2 + sub][1],
                                acc[n16 * 2 + sub][2], acc[n16 * 2 + sub][3],
                                af[0], af[1], af[2], af[3],
                                bfr[n16][sub * 2 + 0], bfr[n16][sub * 2 + 1]);
            }
        }
        if (phase == 1) CP_WAIT0();   // x tile arrived (G4)
        __syncthreads();

        if (phase == 0) {
            // prefetch epilogue x tile (64ch x 128j fp32) into dead V0/A0/B0
            #pragma unroll
            for (int it = 0; it < 8; it++) {
                int idx = tid + it * 256;
                int c = idx >> 5, jseg = idx & 31;
                const char* gsrc = (const char*)(x + ((size_t)(vc0 + c) * HH + i) * WW)
                                   + jseg * 16;
                uint32_t dstoff = (c < 32) ? (uint32_t)(AT_V0 + c * 512)
                                : (c < 48) ? (uint32_t)(AT_A0 + (c - 32) * 512)
                                           : (uint32_t)(AT_B0 + (c - 48) * 512);
                CP_ASYNC16(smb + dstoff + jseg * 16, gsrc);
            }
            CP_COMMIT();              // G4
        }
    }

    // ---- epilogue: x from smem staging ----
    const float gm = gamma[0];
    const int jb = wid * 16 + (lane >> 2);
    #pragma unroll
    for (int ni = 0; ni < 8; ni++) {
        int c0 = ni * 8 + (lane & 3) * 2;
        uint32_t xbase = (ni < 4) ? (uint32_t)(AT_V0 + c0 * 512)
                      : (ni < 6) ? (uint32_t)(AT_A0 + (c0 - 32) * 512)
                                 : (uint32_t)(AT_B0 + (c0 - 48) * 512);
        #pragma unroll
        for (int hf = 0; hf < 2; hf++) {
            int j = jb + hf * 8;
            size_t off0 = (((size_t)vc0 + c0) * HH + i) * WW + j;
            size_t off1 = off0 + HWS;
            float x0 = *(const float*)(smem + xbase + j * 4);
            float x1 = *(const float*)(smem + xbase + 512 + j * 4);
            out[off0] = gm * acc[ni][hf * 2 + 0] + x0;
            out[off1] = gm * acc[ni][hf * 2 + 1] + x1;
        }
    }
}

// ---------------------------------------------------------------------------
extern "C" void kernel_launch(void* const* d_in, const int* in_sizes, int n_in,
                              void* d_out, int out_size)
{
    const float* x     = (const float*)d_in[0];
    const float* Wq    = (const float*)d_in[1];
    const float* bq    = (const float*)d_in[2];
    const float* Wk    = (const float*)d_in[3];
    const float* bk    = (const float*)d_in[4];
    const float* Wv    = (const float*)d_in[5];
    const float* bv    = (const float*)d_in[6];
    const float* gamma = (const float*)d_in[7];
    float* out = (float*)d_out;

    cudaFuncSetAttribute(attn_kernel, cudaFuncAttributeMaxDynamicSharedMemorySize,
                         AT_SMEM);
    cudaFuncSetAttribute(proj_mma_kernel, cudaFuncAttributeMaxDynamicSharedMemorySize,
                         65536);

    prep_w_kernel<<<384, 256>>>(Wq, Wk, Wv);
    prep_x_kernel<<<dim3(256, 4, NB), 256>>>(x);
    proj_mma_kernel<<<dim3(128, 3, NB), 256, 65536>>>(bq, bk, bv);
    transpose_kernel<<<dim3(2, 2, 1536), 256>>>();
    attn_kernel<<<dim3(HH, NB * 4), 256, AT_SMEM>>>(x, gamma, out);
}

// round 14
// speedup vs baseline: 1.0425x; 1.0061x over previous
#include <cuda_runtime.h>
#include <cuda_bf16.h>
#include <cuda_fp16.h>
#include <cstdint>

#define HH 128
#define WW 128
#define HWS 16384
#define NB 4
#define KP 512   // split-K storage: [hi(256) | lo(256)]; 12 virtual chunks at GEMM

// ---------------- scratch (device globals; allocation-free rule) ------------
__device__ __align__(16) __nv_bfloat16 g_qhi[(size_t)NB * 32 * HWS];
__device__ __align__(16) __nv_bfloat16 g_qlo[(size_t)NB * 32 * HWS];
__device__ __align__(16) __nv_bfloat16 g_khi[(size_t)NB * 32 * HWS];
__device__ __align__(16) __nv_bfloat16 g_klo[(size_t)NB * 32 * HWS];
__device__ __align__(16) __nv_bfloat16 g_qhiT[(size_t)NB * 32 * HWS];
__device__ __align__(16) __nv_bfloat16 g_qloT[(size_t)NB * 32 * HWS];
__device__ __align__(16) __nv_bfloat16 g_khiT[(size_t)NB * 32 * HWS];
__device__ __align__(16) __nv_bfloat16 g_kloT[(size_t)NB * 32 * HWS];
__device__ __align__(16) __half g_v [(size_t)NB * 256 * HWS];
__device__ __align__(16) __half g_vT[(size_t)NB * 256 * HWS];
__device__ __align__(16) __nv_bfloat16 g_wsplit[(size_t)384 * KP];       // [m][hi|lo]
__device__ __align__(16) __nv_bfloat16 g_xt[(size_t)NB * HWS * KP];      // [b][p][hi|lo]

// single TU-wide dynamic smem symbol (char; cast per-kernel)
extern __shared__ __align__(1024) char smem_raw[];

static __device__ __forceinline__ uint32_t sw128(uint32_t off) {
    return off ^ ((off >> 3) & 0x70);
}
static __device__ __forceinline__ uint32_t sw256(uint32_t off) {
    return off ^ (((off >> 8) & 7) << 4);
}
__device__ __forceinline__ uint32_t smem_u32(const void* p) {
    uint32_t a;
    asm("{ .reg .u64 t; cvta.to.shared.u64 t, %1; cvt.u32.u64 %0, t; }"
        : "=r"(a) : "l"(p));
    return a;
}
__device__ __forceinline__ void ldmatrix_x4(uint32_t& r0, uint32_t& r1,
                                            uint32_t& r2, uint32_t& r3, uint32_t addr) {
    asm volatile("ldmatrix.sync.aligned.m8n8.x4.shared.b16 {%0,%1,%2,%3}, [%4];"
                 : "=r"(r0), "=r"(r1), "=r"(r2), "=r"(r3) : "r"(addr));
}
__device__ __forceinline__ void ldmatrix_x4_trans(uint32_t& r0, uint32_t& r1,
                                                  uint32_t& r2, uint32_t& r3, uint32_t addr) {
    asm volatile("ldmatrix.sync.aligned.m8n8.x4.trans.shared.b16 {%0,%1,%2,%3}, [%4];"
                 : "=r"(r0), "=r"(r1), "=r"(r2), "=r"(r3) : "r"(addr));
}
__device__ __forceinline__ void mma_bf16(float& d0, float& d1, float& d2, float& d3,
                                         uint32_t a0, uint32_t a1, uint32_t a2, uint32_t a3,
                                         uint32_t b0, uint32_t b1) {
    asm volatile("mma.sync.aligned.m16n8k16.row.col.f32.bf16.bf16.f32 "
                 "{%0,%1,%2,%3}, {%4,%5,%6,%7}, {%8,%9}, {%0,%1,%2,%3};"
                 : "+f"(d0), "+f"(d1), "+f"(d2), "+f"(d3)
                 : "r"(a0), "r"(a1), "r"(a2), "r"(a3), "r"(b0), "r"(b1));
}
__device__ __forceinline__ void mma_f16(float& d0, float& d1, float& d2, float& d3,
                                        uint32_t a0, uint32_t a1, uint32_t a2, uint32_t a3,
                                        uint32_t b0, uint32_t b1) {
    asm volatile("mma.sync.aligned.m16n8k16.row.col.f32.f16.f16.f32 "
                 "{%0,%1,%2,%3}, {%4,%5,%6,%7}, {%8,%9}, {%0,%1,%2,%3};"
                 : "+f"(d0), "+f"(d1), "+f"(d2), "+f"(d3)
                 : "r"(a0), "r"(a1), "r"(a2), "r"(a3), "r"(b0), "r"(b1));
}
#define CP_ASYNC16(dst, src) \
    asm volatile("cp.async.cg.shared.global [%0], [%1], 16;" :: "r"(dst), "l"(src))
#define CP_COMMIT() asm volatile("cp.async.commit_group;" ::: "memory")
#define CP_WAIT2()  asm volatile("cp.async.wait_group 2;" ::: "memory")
#define CP_WAIT1()  asm volatile("cp.async.wait_group 1;" ::: "memory")
#define CP_WAIT0()  asm volatile("cp.async.wait_group 0;" ::: "memory")

// ---------------------------------------------------------------------------
// prep_w: W' bf16 [384][512]; rows 0-255 Wv, 256-287 Wq, 288-319 Wk, 320-383 0
// ---------------------------------------------------------------------------
__global__ void prep_w_kernel(const float* __restrict__ Wq, const float* __restrict__ Wk,
                              const float* __restrict__ Wv)
{
    const int m = blockIdx.x;
    const int c = threadIdx.x;
    float w = 0.0f;
    if (m < 256)      w = Wv[m * 256 + c];
    else if (m < 288) w = Wq[(m - 256) * 256 + c];
    else if (m < 320) w = Wk[(m - 288) * 256 + c];
    __nv_bfloat16 hi = __float2bfloat16(w);
    __nv_bfloat16 lo = __float2bfloat16(w - __bfloat162float(hi));
    g_wsplit[(size_t)m * KP + c]       = hi;
    g_wsplit[(size_t)m * KP + 256 + c] = lo;
}

// ---------------------------------------------------------------------------
// prep_x: XT' bf16 [b][p][512]: cols [0:256)=hi, [256:512)=lo
// ---------------------------------------------------------------------------
__global__ void prep_x_kernel(const float* __restrict__ x)
{
    __shared__ float sm[64][65];
    const int b = blockIdx.z, ct = blockIdx.y, pt = blockIdx.x;
    const int c0 = ct * 64, p0 = pt * 64;
    const int t = threadIdx.x;
    const int pj = t & 63, ci0 = t >> 6;
    const float* xb = x + ((size_t)b * 256 + c0) * HWS + p0;
    #pragma unroll
    for (int i = 0; i < 16; i++) {
        int ci = ci0 + i * 4;
        sm[ci][pj] = xb[(size_t)ci * HWS + pj];
    }
    __syncthreads();
    const int cp = t & 31, pl = t >> 5;
    #pragma unroll
    for (int i = 0; i < 8; i++) {
        int p = pl + i * 8;
        float f0 = sm[2 * cp][p], f1 = sm[2 * cp + 1][p];
        __nv_bfloat16 h0 = __float2bfloat16(f0), h1 = __float2bfloat16(f1);
        __nv_bfloat16 l0 = __float2bfloat16(f0 - __bfloat162float(h0));
        __nv_bfloat16 l1 = __float2bfloat16(f1 - __bfloat162float(h1));
        __nv_bfloat162 hp; hp.x = h0; hp.y = h1;
        __nv_bfloat162 lp; lp.x = l0; lp.y = l1;
        __nv_bfloat16* row = g_xt + ((size_t)b * HWS + p0 + p) * KP;
        *(__nv_bfloat162*)(row + c0 + 2 * cp)       = hp;
        *(__nv_bfloat162*)(row + 256 + c0 + 2 * cp) = lp;
    }
}

// ---------------------------------------------------------------------------
// proj_mma: 2-stage cp.async double-buffered bf16 mma GEMM.
// GRID ORDER: mt fastest (blockIdx.x) so the 3 mt-blocks sharing one B stripe
// (same pt,b) run concurrently -> B read hits L2 instead of 3x DRAM.
// ---------------------------------------------------------------------------
__constant__ int ACH[12] = {0, 1, 2, 3, 0, 1, 2, 3, 4, 5, 6, 7};
__constant__ int BCH[12] = {0, 1, 2, 3, 4, 5, 6, 7, 0, 1, 2, 3};

__global__ void __launch_bounds__(256) proj_mma_kernel(
    const float* __restrict__ bq, const float* __restrict__ bk,
    const float* __restrict__ bv)
{
    char* smem = smem_raw;
    const uint32_t smem_base = smem_u32(smem);
    const int tid = threadIdx.x;
    const int wid = tid >> 5, lane = tid & 31;
    const int warp_m = wid & 1;
    const int warp_n = wid >> 1;
    const int mt = blockIdx.x, pt = blockIdx.y, b = blockIdx.z;
    const bool mma_active = (mt < 2) || (warp_m == 0);

    const char* Abase = (const char*)(g_wsplit + (size_t)mt * 128 * KP);
    const char* Bbase = (const char*)(g_xt + ((size_t)b * HWS + pt * 128) * KP);

    float acc[4][4][4];
    #pragma unroll
    for (int i = 0; i < 4; i++)
        #pragma unroll
        for (int j = 0; j < 4; j++)
            #pragma unroll
            for (int k = 0; k < 4; k++) acc[i][j][k] = 0.0f;

    const int a_row_in = lane & 15;
    const int a_kseg   = (lane >> 4) << 4;
    const int b_row_in = (lane & 7) + ((lane >> 4) << 3);
    const int b_kseg   = ((lane >> 3) & 1) << 4;

    const int ld_row = tid >> 3, ld_seg = tid & 7;

    auto issue = [&](int ch, int st) {
        const size_t a0b = (size_t)ACH[ch] * 128;
        const size_t b0b = (size_t)BCH[ch] * 128;
        const uint32_t sb = smem_base + st * 32768;
        #pragma unroll
        for (int r = 0; r < 4; r++) {
            int row = ld_row + r * 32;
            uint32_t so = sw128((uint32_t)(row * 128 + ld_seg * 16));
            CP_ASYNC16(sb + so,         Abase + (size_t)row * (KP * 2) + a0b + ld_seg * 16);
            CP_ASYNC16(sb + 16384 + so, Bbase + (size_t)row * (KP * 2) + b0b + ld_seg * 16);
        }
    };

    issue(0, 0);
    CP_COMMIT();

    for (int ch = 0; ch < 12; ch++) {
        const int st = ch & 1;
        if (ch + 1 < 12) issue(ch + 1, st ^ 1);
        CP_COMMIT();
        CP_WAIT1();
        __syncthreads();

        if (mma_active) {
            const uint32_t sA_u = smem_base + st * 32768;
            const uint32_t sB_u = sA_u + 16384;
            #pragma unroll
            for (int kk = 0; kk < 4; kk++) {
                uint32_t af[4][4];
                #pragma unroll
                for (int mi = 0; mi < 4; mi++) {
                    int row = warp_m * 64 + mi * 16 + a_row_in;
                    ldmatrix_x4(af[mi][0], af[mi][1], af[mi][2], af[mi][3],
                                sA_u + sw128((uint32_t)(row * 128 + kk * 32 + a_kseg)));
                }
                uint32_t bf[2][4];
                #pragma unroll
                for (int ni16 = 0; ni16 < 2; ni16++) {
                    int row = warp_n * 32 + ni16 * 16 + b_row_in;
                    ldmatrix_x4(bf[ni16][0], bf[ni16][1], bf[ni16][2], bf[ni16][3],
                                sB_u + sw128((uint32_t)(row * 128 + kk * 32 + b_kseg)));
                }
                #pragma unroll
                for (int mi = 0; mi < 4; mi++)
                    #pragma unroll
                    for (int ni = 0; ni < 4; ni++)
                        mma_bf16(acc[mi][ni][0], acc[mi][ni][1], acc[mi][ni][2], acc[mi][ni][3],
                                 af[mi][0], af[mi][1], af[mi][2], af[mi][3],
                                 bf[ni >> 1][(ni & 1) * 2 + 0], bf[ni >> 1][(ni & 1) * 2 + 1]);
            }
        }
        __syncthreads();
    }

    const int p0 = pt * 128 + warp_n * 32 + 2 * (lane & 3);
    #pragma unroll
    for (int mi = 0; mi < 4; mi++) {
        #pragma unroll
        for (int half = 0; half < 2; half++) {
            int m = mt * 128 + warp_m * 64 + mi * 16 + (lane >> 2) + half * 8;
            #pragma unroll
            for (int ni = 0; ni < 4; ni++) {
                float v0 = acc[mi][ni][half * 2 + 0];
                float v1 = acc[mi][ni][half * 2 + 1];
                int p = p0 + ni * 8;
                if (m < 256) {
                    float bias = bv[m];
                    __half2 hv = __floats2half2_rn(v0 + bias, v1 + bias);
                    *(__half2*)&g_v[((size_t)b * 256 + m) * HWS + p] = hv;
                } else if (m < 320) {
                    const bool isq = (m < 288);
                    int c = isq ? (m - 256) : (m - 288);
                    float bias = isq ? bq[c] : bk[c];
                    float f0 = v0 + bias, f1 = v1 + bias;
                    __nv_bfloat16 h0 = __float2bfloat16(f0), h1 = __float2bfloat16(f1);
                    __nv_bfloat16 l0 = __float2bfloat16(f0 - __bfloat162float(h0));
                    __nv_bfloat16 l1 = __float2bfloat16(f1 - __bfloat162float(h1));
                    __nv_bfloat162 hp; hp.x = h0; hp.y = h1;
                    __nv_bfloat162 lp; lp.x = l0; lp.y = l1;
                    size_t off = ((size_t)b * 32 + c) * HWS + p;
                    if (isq) {
                        *(__nv_bfloat162*)&g_qhi[off] = hp;
                        *(__nv_bfloat162*)&g_qlo[off] = lp;
                    } else {
                        *(__nv_bfloat162*)&g_khi[off] = hp;
                        *(__nv_bfloat162*)&g_klo[off] = lp;
                    }
                }
            }
        }
    }
}

// ---------------------------------------------------------------------------
// transpose: 16-bit planes [H][W] -> [W][H]; 64x64 tiles, uint32 vectorized.
// ---------------------------------------------------------------------------
__global__ void transpose_kernel()
{
    __shared__ uint16_t sm[64][70];
    const int plane = blockIdx.z;
    const uint16_t* src;
    uint16_t* dst;
    if (plane < 512) {
        int t = plane >> 7, ch = plane & 127;
        const __nv_bfloat16* s;
        __nv_bfloat16* d;
        switch (t) {
            case 0:  s = g_qhi; d = g_qhiT; break;
            case 1:  s = g_qlo; d = g_qloT; break;
            case 2:  s = g_khi; d = g_khiT; break;
            default: s = g_klo; d = g_kloT; break;
        }
        src = (const uint16_t*)(s + (size_t)ch * HWS);
        dst = (uint16_t*)(d + (size_t)ch * HWS);
    } else {
        int ch = plane - 512;
        src = (const uint16_t*)(g_v + (size_t)ch * HWS);
        dst = (uint16_t*)(g_vT + (size_t)ch * HWS);
    }
    const int ti = blockIdx.y * 64, tj = blockIdx.x * 64;
    const int t = threadIdx.x;
    const int cw = (t & 31) * 2, r0 = t >> 5;
    #pragma unroll
    for (int p = 0; p < 8; p++) {
        int r = r0 + p * 8;
        *(uint32_t*)&sm[r][cw] = *(const uint32_t*)&src[(size_t)(ti + r) * WW + tj + cw];
    }
    __syncthreads();
    const int ch2 = (t & 31) * 2, w0 = t >> 5;
    #pragma unroll
    for (int p = 0; p < 8; p++) {
        int w = w0 + p * 8;
        uint32_t v = (uint32_t)sm[ch2][w] | ((uint32_t)sm[ch2 + 1][w] << 16);
        *(uint32_t*)&dst[(size_t)(tj + w) * HH + ti + ch2] = v;
    }
}

// ---------------------------------------------------------------------------
// Tensor-core criss-cross attention (unchanged from 227.5 baseline).
// cp.async groups: G1=A0/B0, G2=V0, G3=A1/B1/V1, G4=x epilogue tile.
// ---------------------------------------------------------------------------
#define AT_P    0
#define AT_V0   32768
#define AT_V1   49152
#define AT_A0   65536
#define AT_A1   73728
#define AT_B0   81920
#define AT_B1   90112
#define AT_SSUM 98304
#define AT_SMEM (98304 + 1024)

__global__ void __launch_bounds__(256, 2) attn_kernel(
    const float* __restrict__ x, const float* __restrict__ gamma,
    float* __restrict__ out)
{
    char* smem = smem_raw;
    float* ssum = (float*)(smem + AT_SSUM);

    const int i  = blockIdx.x;
    const int bh = blockIdx.y;
    const int b = bh >> 2, h = bh & 3;
    const int tid = threadIdx.x;
    const int wid = tid >> 5, lane = tid & 31;

    const uint32_t smb  = smem_u32(smem);
    const uint32_t sP_u = smb + AT_P;

    const int b_row_in = (lane & 7) + ((lane >> 4) << 3);
    const int b_kseg   = ((lane >> 3) & 1) << 4;
    const int tr_row_a = (lane & 7) + (((lane >> 4) & 1) << 3);
    const int tr_col_a = ((lane >> 3) & 1) << 3;
    const int tr_row_b = (lane & 7) + (((lane >> 3) & 1) << 3);
    const int tr_col_b = ((lane >> 4) & 1) << 3;

    const int em = wid & 1, en = wid >> 1;

    const int qkc0 = (b * 32 + h * 8);
    const int vc0  = (b * 256 + h * 64);
    const int loff = i * 128;

    // zero pad rows 24-31 of A0/A1/B0/B1 (persist across phases)
    #pragma unroll
    for (int z = 0; z < 2; z++) {
        int idx = tid + z * 256;
        int bufsel = idx >> 7;
        int r = 24 + ((idx >> 4) & 7), chunk = idx & 15;
        uint32_t base = (bufsel == 0) ? AT_A0 : (bufsel == 1) ? AT_A1
                       : (bufsel == 2) ? AT_B0 : AT_B1;
        *(uint4*)(smem + base + sw256((uint32_t)(r * 256 + chunk * 16))) =
            make_uint4(0, 0, 0, 0);
    }

    auto issue_AB = [&](int ph) {
        const __nv_bfloat16* Khi = ph ? g_khiT : g_khi;
        const __nv_bfloat16* Klo = ph ? g_kloT : g_klo;
        const __nv_bfloat16* Qhi = ph ? g_qhiT : g_qhi;
        const __nv_bfloat16* Qlo = ph ? g_qloT : g_qlo;
        const uint32_t aU = smb + (ph ? AT_A1 : AT_A0);
        const uint32_t bU = smb + (ph ? AT_B1 : AT_B0);
        #pragma unroll
        for (int it = 0; it < 3; it++) {
            int idx = tid + it * 256;
            int rr2 = idx >> 4, chunk = idx & 15;
            int tile = rr2 >= 24;
            int r = tile ? (rr2 - 24) : rr2;
            int c = r & 7;
            const __nv_bfloat16* src;
            if (!tile) src = (r < 16) ? Khi : Klo;
            else       src = (r >= 8 && r < 16) ? Qlo : Qhi;
            const char* gsrc = (const char*)(src + (size_t)(qkc0 + c) * HWS + loff) + chunk * 16;
            uint32_t dst = (tile ? bU : aU) + sw256((uint32_t)(r * 256 + chunk * 16));
            CP_ASYNC16(dst, gsrc);
        }
    };
    auto issue_V = [&](int ph) {
        const __half* Vp = ph ? g_vT : g_v;
        const uint32_t vU = smb + (ph ? AT_V1 : AT_V0);
        #pragma unroll
        for (int it = 0; it < 4; it++) {
            int idx = tid + it * 256;
            int c = idx >> 4, chunk = idx & 15;
            const char* gsrc = (const char*)(Vp + (size_t)(vc0 + c) * HWS + loff) + chunk * 16;
            CP_ASYNC16(vU + sw256((uint32_t)(c * 256 + chunk * 16)), gsrc);
        }
    };

    issue_AB(0); CP_COMMIT();                 // G1
    issue_V(0);  CP_COMMIT();                 // G2
    issue_AB(1); issue_V(1); CP_COMMIT();     // G3

    float acc[8][4];
    #pragma unroll
    for (int ni = 0; ni < 8; ni++)
        #pragma unroll
        for (int k = 0; k < 4; k++) acc[ni][k] = 0.0f;

    for (int phase = 0; phase < 2; phase++) {
        const uint32_t sA_u = smb + (phase ? AT_A1 : AT_A0);
        const uint32_t sB_u = smb + (phase ? AT_B1 : AT_B0);
        const uint32_t sV_u = smb + (phase ? AT_V1 : AT_V0);
        if (phase == 0) { CP_WAIT2(); } else { CP_WAIT1(); }
        __syncthreads();

        // ---- energy mma: A,B via trans-ldmatrix from [c'][g] tiles ----
        float ef[4][4][4];
        #pragma unroll
        for (int mi = 0; mi < 4; mi++)
            #pragma unroll
            for (int ni = 0; ni < 4; ni++)
                #pragma unroll
                for (int k = 0; k < 4; k++) ef[mi][ni][k] = 0.0f;
        #pragma unroll
        for (int ks = 0; ks < 2; ks++) {
            uint32_t af[4][4];
            #pragma unroll
            for (int mi = 0; mi < 4; mi++) {
                int row = ks * 16 + tr_row_a;
                int col = em * 64 + mi * 16 + tr_col_a;
                ldmatrix_x4_trans(af[mi][0], af[mi][1], af[mi][2], af[mi][3],
                                  sA_u + sw256((uint32_t)(row * 256 + col * 2)));
            }
            uint32_t bfr[2][4];
            #pragma unroll
            for (int n16 = 0; n16 < 2; n16++) {
                int row = ks * 16 + tr_row_b;
                int col = en * 32 + n16 * 16 + tr_col_b;
                ldmatrix_x4_trans(bfr[n16][0], bfr[n16][1], bfr[n16][2], bfr[n16][3],
                                  sB_u + sw256((uint32_t)(row * 256 + col * 2)));
            }
            #pragma unroll
            for (int mi = 0; mi < 4; mi++)
                #pragma unroll
                for (int ni = 0; ni < 4; ni++)
                    mma_bf16(ef[mi][ni][0], ef[mi][ni][1], ef[mi][ni][2], ef[mi][ni][3],
                             af[mi][0], af[mi][1], af[mi][2], af[mi][3],
                             bfr[ni >> 1][(ni & 1) * 2 + 0], bfr[ni >> 1][(ni & 1) * 2 + 1]);
        }

        // ---- exp in registers + per-j column sums ----
        float psum[4][2];
        #pragma unroll
        for (int ni = 0; ni < 4; ni++) { psum[ni][0] = 0.0f; psum[ni][1] = 0.0f; }
        #pragma unroll
        for (int mi = 0; mi < 4; mi++)
            #pragma unroll
            for (int ni = 0; ni < 4; ni++) {
                ef[mi][ni][0] = __expf(ef[mi][ni][0]);
                ef[mi][ni][1] = __expf(ef[mi][ni][1]);
                ef[mi][ni][2] = __expf(ef[mi][ni][2]);
                ef[mi][ni][3] = __expf(ef[mi][ni][3]);
                psum[ni][0] += ef[mi][ni][0] + ef[mi][ni][2];
                psum[ni][1] += ef[mi][ni][1] + ef[mi][ni][3];
            }
        #pragma unroll
        for (int ni = 0; ni < 4; ni++) {
            #pragma unroll
            for (int d = 4; d <= 16; d <<= 1) {
                psum[ni][0] += __shfl_xor_sync(0xffffffffu, psum[ni][0], d);
                psum[ni][1] += __shfl_xor_sync(0xffffffffu, psum[ni][1], d);
            }
        }
        if ((lane >> 2) == 0) {
            #pragma unroll
            for (int ni = 0; ni < 4; ni++) {
                int j0 = en * 32 + ni * 8 + (lane & 3) * 2;
                *(float2*)&ssum[em * 128 + j0] = make_float2(psum[ni][0], psum[ni][1]);
            }
        }
        __syncthreads();

        // ---- normalize + store P fp16 [g][j] ----
        #pragma unroll
        for (int ni = 0; ni < 4; ni++) {
            int j0 = en * 32 + ni * 8 + (lane & 3) * 2;
            float2 sa = *(float2*)&ssum[j0];
            float2 sb = *(float2*)&ssum[128 + j0];
            float is0 = 1.0f / (sa.x + sb.x);
            float is1 = 1.0f / (sa.y + sb.y);
            #pragma unroll
            for (int mi = 0; mi < 4; mi++) {
                int g0 = em * 64 + mi * 16 + (lane >> 2);
                __half2 p0 = __floats2half2_rn(ef[mi][ni][0] * is0, ef[mi][ni][1] * is1);
                __half2 p1 = __floats2half2_rn(ef[mi][ni][2] * is0, ef[mi][ni][3] * is1);
                *(uint32_t*)(smem + AT_P + sw256((uint32_t)(g0 * 256 + j0 * 2)))       = *(uint32_t*)&p0;
                *(uint32_t*)(smem + AT_P + sw256((uint32_t)((g0 + 8) * 256 + j0 * 2))) = *(uint32_t*)&p1;
            }
        }
        if (phase == 0) CP_WAIT1();   // V0 arrived (G2)
        __syncthreads();

        // ---- O mma: A = P (m=j, k=g, trans), B = V (n=c, k=g) ----
        {
            #pragma unroll
            for (int ks = 0; ks < 8; ks++) {
                uint32_t af[4];
                {
                    int row = ks * 16 + tr_row_a;
                    int col = wid * 16 + tr_col_a;
                    ldmatrix_x4_trans(af[0], af[1], af[2], af[3],
                                      sP_u + sw256((uint32_t)(row * 256 + col * 2)));
                }
                uint32_t bfr[4][4];
                #pragma unroll
                for (int n16 = 0; n16 < 4; n16++) {
                    int row = n16 * 16 + b_row_in;
                    ldmatrix_x4(bfr[n16][0], bfr[n16][1], bfr[n16][2], bfr[n16][3],
                                sV_u + sw256((uint32_t)(row * 256 + ks * 32) + (uint32_t)b_kseg));
                }
                #pragma unroll
                for (int n16 = 0; n16 < 4; n16++)
                    #pragma unroll
                    for (int sub = 0; sub < 2; sub++)
                        mma_f16(acc[n16 * 2 + sub][0], acc[n16 * 2 + sub][1],
                                acc[n16 * 2 + sub][2], acc[n16 * 2 + sub][3],
                                af[0], af[1], af[2], af[3],
                                bfr[n16][sub * 2 + 0], bfr[n16][sub * 2 + 1]);
            }
        }
        if (phase == 1) CP_WAIT0();   // x tile arrived (G4)
        __syncthreads();

        if (phase == 0) {
            // prefetch epilogue x tile (64ch x 128j fp32) into dead V0/A0/B0
            #pragma unroll
            for (int it = 0; it < 8; it++) {
                int idx = tid + it * 256;
                int c = idx >> 5, jseg = idx & 31;
                const char* gsrc = (const char*)(x + ((size_t)(vc0 + c) * HH + i) * WW)
                                   + jseg * 16;
                uint32_t dstoff = (c < 32) ? (uint32_t)(AT_V0 + c * 512)
                                : (c < 48) ? (uint32_t)(AT_A0 + (c - 32) * 512)
                                           : (uint32_t)(AT_B0 + (c - 48) * 512);
                CP_ASYNC16(smb + dstoff + jseg * 16, gsrc);
            }
            CP_COMMIT();              // G4
        }
    }

    // ---- epilogue: x from smem staging ----
    const float gm = gamma[0];
    const int jb = wid * 16 + (lane >> 2);
    #pragma unroll
    for (int ni = 0; ni < 8; ni++) {
        int c0 = ni * 8 + (lane & 3) * 2;
        uint32_t xbase = (ni < 4) ? (uint32_t)(AT_V0 + c0 * 512)
                      : (ni < 6) ? (uint32_t)(AT_A0 + (c0 - 32) * 512)
                                 : (uint32_t)(AT_B0 + (c0 - 48) * 512);
        #pragma unroll
        for (int hf = 0; hf < 2; hf++) {
            int j = jb + hf * 8;
            size_t off0 = (((size_t)vc0 + c0) * HH + i) * WW + j;
            size_t off1 = off0 + HWS;
            float x0 = *(const float*)(smem + xbase + j * 4);
            float x1 = *(const float*)(smem + xbase + 512 + j * 4);
            out[off0] = gm * acc[ni][hf * 2 + 0] + x0;
            out[off1] = gm * acc[ni][hf * 2 + 1] + x1;
        }
    }
}

// ---------------------------------------------------------------------------
extern "C" void kernel_launch(void* const* d_in, const int* in_sizes, int n_in,
                              void* d_out, int out_size)
{
    const float* x     = (const float*)d_in[0];
    const float* Wq    = (const float*)d_in[1];
    const float* bq    = (const float*)d_in[2];
    const float* Wk    = (const float*)d_in[3];
    const float* bk    = (const float*)d_in[4];
    const float* Wv    = (const float*)d_in[5];
    const float* bv    = (const float*)d_in[6];
    const float* gamma = (const float*)d_in[7];
    float* out = (float*)d_out;

    cudaFuncSetAttribute(attn_kernel, cudaFuncAttributeMaxDynamicSharedMemorySize,
                         AT_SMEM);
    cudaFuncSetAttribute(proj_mma_kernel, cudaFuncAttributeMaxDynamicSharedMemorySize,
                         65536);

    prep_w_kernel<<<384, 256>>>(Wq, Wk, Wv);
    prep_x_kernel<<<dim3(256, 4, NB), 256>>>(x);
    proj_mma_kernel<<<dim3(3, 128, NB), 256, 65536>>>(bq, bk, bv);
    transpose_kernel<<<dim3(2, 2, 1536), 256>>>();
    attn_kernel<<<dim3(HH, NB * 4), 256, AT_SMEM>>>(x, gamma, out);
}

// round 15
// speedup vs baseline: 1.0635x; 1.0202x over previous
#include <cuda_runtime.h>
#include <cuda_bf16.h>
#include <cuda_fp16.h>
#include <cstdint>

#define HH 128
#define WW 128
#define HWS 16384
#define NB 4
#define KP 512   // split-K storage: [hi(256) | lo(256)]; 12 virtual chunks at GEMM

// ---------------- scratch (device globals; allocation-free rule) ------------
__device__ __align__(16) __nv_bfloat16 g_qhi[(size_t)NB * 32 * HWS];
__device__ __align__(16) __nv_bfloat16 g_qlo[(size_t)NB * 32 * HWS];
__device__ __align__(16) __nv_bfloat16 g_khi[(size_t)NB * 32 * HWS];
__device__ __align__(16) __nv_bfloat16 g_klo[(size_t)NB * 32 * HWS];
__device__ __align__(16) __nv_bfloat16 g_qhiT[(size_t)NB * 32 * HWS];
__device__ __align__(16) __nv_bfloat16 g_qloT[(size_t)NB * 32 * HWS];
__device__ __align__(16) __nv_bfloat16 g_khiT[(size_t)NB * 32 * HWS];
__device__ __align__(16) __nv_bfloat16 g_kloT[(size_t)NB * 32 * HWS];
__device__ __align__(16) __half g_v [(size_t)NB * 256 * HWS];
__device__ __align__(16) __half g_vT[(size_t)NB * 256 * HWS];
__device__ __align__(16) __nv_bfloat16 g_wsplit[(size_t)384 * KP];       // [m][hi|lo]
__device__ __align__(16) __nv_bfloat16 g_xt[(size_t)NB * HWS * KP];      // [b][p][hi|lo]

// single TU-wide dynamic smem symbol (char; cast per-kernel)
extern __shared__ __align__(1024) char smem_raw[];

static __device__ __forceinline__ uint32_t sw128(uint32_t off) {
    return off ^ ((off >> 3) & 0x70);
}
static __device__ __forceinline__ uint32_t sw256(uint32_t off) {
    return off ^ (((off >> 8) & 7) << 4);
}
__device__ __forceinline__ uint32_t smem_u32(const void* p) {
    uint32_t a;
    asm("{ .reg .u64 t; cvta.to.shared.u64 t, %1; cvt.u32.u64 %0, t; }"
        : "=r"(a) : "l"(p));
    return a;
}
__device__ __forceinline__ void ldmatrix_x4(uint32_t& r0, uint32_t& r1,
                                            uint32_t& r2, uint32_t& r3, uint32_t addr) {
    asm volatile("ldmatrix.sync.aligned.m8n8.x4.shared.b16 {%0,%1,%2,%3}, [%4];"
                 : "=r"(r0), "=r"(r1), "=r"(r2), "=r"(r3) : "r"(addr));
}
__device__ __forceinline__ void ldmatrix_x4_trans(uint32_t& r0, uint32_t& r1,
                                                  uint32_t& r2, uint32_t& r3, uint32_t addr) {
    asm volatile("ldmatrix.sync.aligned.m8n8.x4.trans.shared.b16 {%0,%1,%2,%3}, [%4];"
                 : "=r"(r0), "=r"(r1), "=r"(r2), "=r"(r3) : "r"(addr));
}
__device__ __forceinline__ void mma_bf16(float& d0, float& d1, float& d2, float& d3,
                                         uint32_t a0, uint32_t a1, uint32_t a2, uint32_t a3,
                                         uint32_t b0, uint32_t b1) {
    asm volatile("mma.sync.aligned.m16n8k16.row.col.f32.bf16.bf16.f32 "
                 "{%0,%1,%2,%3}, {%4,%5,%6,%7}, {%8,%9}, {%0,%1,%2,%3};"
                 : "+f"(d0), "+f"(d1), "+f"(d2), "+f"(d3)
                 : "r"(a0), "r"(a1), "r"(a2), "r"(a3), "r"(b0), "r"(b1));
}
__device__ __forceinline__ void mma_f16(float& d0, float& d1, float& d2, float& d3,
                                        uint32_t a0, uint32_t a1, uint32_t a2, uint32_t a3,
                                        uint32_t b0, uint32_t b1) {
    asm volatile("mma.sync.aligned.m16n8k16.row.col.f32.f16.f16.f32 "
                 "{%0,%1,%2,%3}, {%4,%5,%6,%7}, {%8,%9}, {%0,%1,%2,%3};"
                 : "+f"(d0), "+f"(d1), "+f"(d2), "+f"(d3)
                 : "r"(a0), "r"(a1), "r"(a2), "r"(a3), "r"(b0), "r"(b1));
}
#define CP_ASYNC16(dst, src) \
    asm volatile("cp.async.cg.shared.global [%0], [%1], 16;" :: "r"(dst), "l"(src))
#define CP_COMMIT() asm volatile("cp.async.commit_group;" ::: "memory")
#define CP_WAIT2()  asm volatile("cp.async.wait_group 2;" ::: "memory")
#define CP_WAIT1()  asm volatile("cp.async.wait_group 1;" ::: "memory")
#define CP_WAIT0()  asm volatile("cp.async.wait_group 0;" ::: "memory")

// ---------------------------------------------------------------------------
// prep_w: W' bf16 [384][512]; rows 0-255 Wv, 256-287 Wq, 288-319 Wk, 320-383 0
// ---------------------------------------------------------------------------
__global__ void prep_w_kernel(const float* __restrict__ Wq, const float* __restrict__ Wk,
                              const float* __restrict__ Wv)
{
    const int m = blockIdx.x;
    const int c = threadIdx.x;
    float w = 0.0f;
    if (m < 256)      w = Wv[m * 256 + c];
    else if (m < 288) w = Wq[(m - 256) * 256 + c];
    else if (m < 320) w = Wk[(m - 288) * 256 + c];
    __nv_bfloat16 hi = __float2bfloat16(w);
    __nv_bfloat16 lo = __float2bfloat16(w - __bfloat162float(hi));
    g_wsplit[(size_t)m * KP + c]       = hi;
    g_wsplit[(size_t)m * KP + 256 + c] = lo;
}

// ---------------------------------------------------------------------------
// prep_x: XT' bf16 [b][p][512]: cols [0:256)=hi, [256:512)=lo
// ---------------------------------------------------------------------------
__global__ void prep_x_kernel(const float* __restrict__ x)
{
    __shared__ float sm[64][65];
    const int b = blockIdx.z, ct = blockIdx.y, pt = blockIdx.x;
    const int c0 = ct * 64, p0 = pt * 64;
    const int t = threadIdx.x;
    const int pj = t & 63, ci0 = t >> 6;
    const float* xb = x + ((size_t)b * 256 + c0) * HWS + p0;
    #pragma unroll
    for (int i = 0; i < 16; i++) {
        int ci = ci0 + i * 4;
        sm[ci][pj] = xb[(size_t)ci * HWS + pj];
    }
    __syncthreads();
    const int cp = t & 31, pl = t >> 5;
    #pragma unroll
    for (int i = 0; i < 8; i++) {
        int p = pl + i * 8;
        float f0 = sm[2 * cp][p], f1 = sm[2 * cp + 1][p];
        __nv_bfloat16 h0 = __float2bfloat16(f0), h1 = __float2bfloat16(f1);
        __nv_bfloat16 l0 = __float2bfloat16(f0 - __bfloat162float(h0));
        __nv_bfloat16 l1 = __float2bfloat16(f1 - __bfloat162float(h1));
        __nv_bfloat162 hp; hp.x = h0; hp.y = h1;
        __nv_bfloat162 lp; lp.x = l0; lp.y = l1;
        __nv_bfloat16* row = g_xt + ((size_t)b * HWS + p0 + p) * KP;
        *(__nv_bfloat162*)(row + c0 + 2 * cp)       = hp;
        *(__nv_bfloat162*)(row + 256 + c0 + 2 * cp) = lp;
    }
}

// ---------------------------------------------------------------------------
// proj_mma: 2-stage cp.async double-buffered bf16 mma GEMM; mt fastest.
// ---------------------------------------------------------------------------
__constant__ int ACH[12] = {0, 1, 2, 3, 0, 1, 2, 3, 4, 5, 6, 7};
__constant__ int BCH[12] = {0, 1, 2, 3, 4, 5, 6, 7, 0, 1, 2, 3};

__global__ void __launch_bounds__(256) proj_mma_kernel(
    const float* __restrict__ bq, const float* __restrict__ bk,
    const float* __restrict__ bv)
{
    char* smem = smem_raw;
    const uint32_t smem_base = smem_u32(smem);
    const int tid = threadIdx.x;
    const int wid = tid >> 5, lane = tid & 31;
    const int warp_m = wid & 1;
    const int warp_n = wid >> 1;
    const int mt = blockIdx.x, pt = blockIdx.y, b = blockIdx.z;
    const bool mma_active = (mt < 2) || (warp_m == 0);

    const char* Abase = (const char*)(g_wsplit + (size_t)mt * 128 * KP);
    const char* Bbase = (const char*)(g_xt + ((size_t)b * HWS + pt * 128) * KP);

    float acc[4][4][4];
    #pragma unroll
    for (int i = 0; i < 4; i++)
        #pragma unroll
        for (int j = 0; j < 4; j++)
            #pragma unroll
            for (int k = 0; k < 4; k++) acc[i][j][k] = 0.0f;

    const int a_row_in = lane & 15;
    const int a_kseg   = (lane >> 4) << 4;
    const int b_row_in = (lane & 7) + ((lane >> 4) << 3);
    const int b_kseg   = ((lane >> 3) & 1) << 4;

    const int ld_row = tid >> 3, ld_seg = tid & 7;

    auto issue = [&](int ch, int st) {
        const size_t a0b = (size_t)ACH[ch] * 128;
        const size_t b0b = (size_t)BCH[ch] * 128;
        const uint32_t sb = smem_base + st * 32768;
        #pragma unroll
        for (int r = 0; r < 4; r++) {
            int row = ld_row + r * 32;
            uint32_t so = sw128((uint32_t)(row * 128 + ld_seg * 16));
            CP_ASYNC16(sb + so,         Abase + (size_t)row * (KP * 2) + a0b + ld_seg * 16);
            CP_ASYNC16(sb + 16384 + so, Bbase + (size_t)row * (KP * 2) + b0b + ld_seg * 16);
        }
    };

    issue(0, 0);
    CP_COMMIT();

    for (int ch = 0; ch < 12; ch++) {
        const int st = ch & 1;
        if (ch + 1 < 12) issue(ch + 1, st ^ 1);
        CP_COMMIT();
        CP_WAIT1();
        __syncthreads();

        if (mma_active) {
            const uint32_t sA_u = smem_base + st * 32768;
            const uint32_t sB_u = sA_u + 16384;
            #pragma unroll
            for (int kk = 0; kk < 4; kk++) {
                uint32_t af[4][4];
                #pragma unroll
                for (int mi = 0; mi < 4; mi++) {
                    int row = warp_m * 64 + mi * 16 + a_row_in;
                    ldmatrix_x4(af[mi][0], af[mi][1], af[mi][2], af[mi][3],
                                sA_u + sw128((uint32_t)(row * 128 + kk * 32 + a_kseg)));
                }
                uint32_t bf[2][4];
                #pragma unroll
                for (int ni16 = 0; ni16 < 2; ni16++) {
                    int row = warp_n * 32 + ni16 * 16 + b_row_in;
                    ldmatrix_x4(bf[ni16][0], bf[ni16][1], bf[ni16][2], bf[ni16][3],
                                sB_u + sw128((uint32_t)(row * 128 + kk * 32 + b_kseg)));
                }
                #pragma unroll
                for (int mi = 0; mi < 4; mi++)
                    #pragma unroll
                    for (int ni = 0; ni < 4; ni++)
                        mma_bf16(acc[mi][ni][0], acc[mi][ni][1], acc[mi][ni][2], acc[mi][ni][3],
                                 af[mi][0], af[mi][1], af[mi][2], af[mi][3],
                                 bf[ni >> 1][(ni & 1) * 2 + 0], bf[ni >> 1][(ni & 1) * 2 + 1]);
            }
        }
        __syncthreads();
    }

    const int p0 = pt * 128 + warp_n * 32 + 2 * (lane & 3);
    #pragma unroll
    for (int mi = 0; mi < 4; mi++) {
        #pragma unroll
        for (int half = 0; half < 2; half++) {
            int m = mt * 128 + warp_m * 64 + mi * 16 + (lane >> 2) + half * 8;
            #pragma unroll
            for (int ni = 0; ni < 4; ni++) {
                float v0 = acc[mi][ni][half * 2 + 0];
                float v1 = acc[mi][ni][half * 2 + 1];
                int p = p0 + ni * 8;
                if (m < 256) {
                    float bias = bv[m];
                    __half2 hv = __floats2half2_rn(v0 + bias, v1 + bias);
                    *(__half2*)&g_v[((size_t)b * 256 + m) * HWS + p] = hv;
                } else if (m < 320) {
                    const bool isq = (m < 288);
                    int c = isq ? (m - 256) : (m - 288);
                    float bias = isq ? bq[c] : bk[c];
                    float f0 = v0 + bias, f1 = v1 + bias;
                    __nv_bfloat16 h0 = __float2bfloat16(f0), h1 = __float2bfloat16(f1);
                    __nv_bfloat16 l0 = __float2bfloat16(f0 - __bfloat162float(h0));
                    __nv_bfloat16 l1 = __float2bfloat16(f1 - __bfloat162float(h1));
                    __nv_bfloat162 hp; hp.x = h0; hp.y = h1;
                    __nv_bfloat162 lp; lp.x = l0; lp.y = l1;
                    size_t off = ((size_t)b * 32 + c) * HWS + p;
                    if (isq) {
                        *(__nv_bfloat162*)&g_qhi[off] = hp;
                        *(__nv_bfloat162*)&g_qlo[off] = lp;
                    } else {
                        *(__nv_bfloat162*)&g_khi[off] = hp;
                        *(__nv_bfloat162*)&g_klo[off] = lp;
                    }
                }
            }
        }
    }
}

// ---------------------------------------------------------------------------
// transpose: 16-bit planes [H][W] -> [W][H]; signals dependent (attn) launch
// immediately — attn's phase-0 data does not depend on transpose output.
// ---------------------------------------------------------------------------
__global__ void transpose_kernel()
{
    asm volatile("griddepcontrol.launch_dependents;");
    __shared__ uint16_t sm[64][70];
    const int plane = blockIdx.z;
    const uint16_t* src;
    uint16_t* dst;
    if (plane < 512) {
        int t = plane >> 7, ch = plane & 127;
        const __nv_bfloat16* s;
        __nv_bfloat16* d;
        switch (t) {
            case 0:  s = g_qhi; d = g_qhiT; break;
            case 1:  s = g_qlo; d = g_qloT; break;
            case 2:  s = g_khi; d = g_khiT; break;
            default: s = g_klo; d = g_kloT; break;
        }
        src = (const uint16_t*)(s + (size_t)ch * HWS);
        dst = (uint16_t*)(d + (size_t)ch * HWS);
    } else {
        int ch = plane - 512;
        src = (const uint16_t*)(g_v + (size_t)ch * HWS);
        dst = (uint16_t*)(g_vT + (size_t)ch * HWS);
    }
    const int ti = blockIdx.y * 64, tj = blockIdx.x * 64;
    const int t = threadIdx.x;
    const int cw = (t & 31) * 2, r0 = t >> 5;
    #pragma unroll
    for (int p = 0; p < 8; p++) {
        int r = r0 + p * 8;
        *(uint32_t*)&sm[r][cw] = *(const uint32_t*)&src[(size_t)(ti + r) * WW + tj + cw];
    }
    __syncthreads();
    const int ch2 = (t & 31) * 2, w0 = t >> 5;
    #pragma unroll
    for (int p = 0; p < 8; p++) {
        int w = w0 + p * 8;
        uint32_t v = (uint32_t)sm[ch2][w] | ((uint32_t)sm[ch2 + 1][w] << 16);
        *(uint32_t*)&dst[(size_t)(tj + w) * HH + ti + ch2] = v;
    }
}

// ---------------------------------------------------------------------------
// Tensor-core criss-cross attention. PDL: launches while transpose still
// runs; G1/G2 (phase-0, non-transposed planes) issue immediately;
// griddepcontrol.wait gates only G3 (T-plane reads).
// ---------------------------------------------------------------------------
#define AT_P    0
#define AT_V0   32768
#define AT_V1   49152
#define AT_A0   65536
#define AT_A1   73728
#define AT_B0   81920
#define AT_B1   90112
#define AT_SSUM 98304
#define AT_SMEM (98304 + 1024)

__global__ void __launch_bounds__(256, 2) attn_kernel(
    const float* __restrict__ x, const float* __restrict__ gamma,
    float* __restrict__ out)
{
    char* smem = smem_raw;
    float* ssum = (float*)(smem + AT_SSUM);

    const int i  = blockIdx.x;
    const int bh = blockIdx.y;
    const int b = bh >> 2, h = bh & 3;
    const int tid = threadIdx.x;
    const int wid = tid >> 5, lane = tid & 31;

    const uint32_t smb  = smem_u32(smem);
    const uint32_t sP_u = smb + AT_P;

    const int b_row_in = (lane & 7) + ((lane >> 4) << 3);
    const int b_kseg   = ((lane >> 3) & 1) << 4;
    const int tr_row_a = (lane & 7) + (((lane >> 4) & 1) << 3);
    const int tr_col_a = ((lane >> 3) & 1) << 3;
    const int tr_row_b = (lane & 7) + (((lane >> 3) & 1) << 3);
    const int tr_col_b = ((lane >> 4) & 1) << 3;

    const int em = wid & 1, en = wid >> 1;

    const int qkc0 = (b * 32 + h * 8);
    const int vc0  = (b * 256 + h * 64);
    const int loff = i * 128;

    // zero pad rows 24-31 of A0/A1/B0/B1 (persist across phases)
    #pragma unroll
    for (int z = 0; z < 2; z++) {
        int idx = tid + z * 256;
        int bufsel = idx >> 7;
        int r = 24 + ((idx >> 4) & 7), chunk = idx & 15;
        uint32_t base = (bufsel == 0) ? AT_A0 : (bufsel == 1) ? AT_A1
                       : (bufsel == 2) ? AT_B0 : AT_B1;
        *(uint4*)(smem + base + sw256((uint32_t)(r * 256 + chunk * 16))) =
            make_uint4(0, 0, 0, 0);
    }

    auto issue_AB = [&](int ph) {
        const __nv_bfloat16* Khi = ph ? g_khiT : g_khi;
        const __nv_bfloat16* Klo = ph ? g_kloT : g_klo;
        const __nv_bfloat16* Qhi = ph ? g_qhiT : g_qhi;
        const __nv_bfloat16* Qlo = ph ? g_qloT : g_qlo;
        const uint32_t aU = smb + (ph ? AT_A1 : AT_A0);
        const uint32_t bU = smb + (ph ? AT_B1 : AT_B0);
        #pragma unroll
        for (int it = 0; it < 3; it++) {
            int idx = tid + it * 256;
            int rr2 = idx >> 4, chunk = idx & 15;
            int tile = rr2 >= 24;
            int r = tile ? (rr2 - 24) : rr2;
            int c = r & 7;
            const __nv_bfloat16* src;
            if (!tile) src = (r < 16) ? Khi : Klo;
            else       src = (r >= 8 && r < 16) ? Qlo : Qhi;
            const char* gsrc = (const char*)(src + (size_t)(qkc0 + c) * HWS + loff) + chunk * 16;
            uint32_t dst = (tile ? bU : aU) + sw256((uint32_t)(r * 256 + chunk * 16));
            CP_ASYNC16(dst, gsrc);
        }
    };
    auto issue_V = [&](int ph) {
        const __half* Vp = ph ? g_vT : g_v;
        const uint32_t vU = smb + (ph ? AT_V1 : AT_V0);
        #pragma unroll
        for (int it = 0; it < 4; it++) {
            int idx = tid + it * 256;
            int c = idx >> 4, chunk = idx & 15;
            const char* gsrc = (const char*)(Vp + (size_t)(vc0 + c) * HWS + loff) + chunk * 16;
            CP_ASYNC16(vU + sw256((uint32_t)(c * 256 + chunk * 16)), gsrc);
        }
    };

    issue_AB(0); CP_COMMIT();                 // G1 (non-T: safe pre-wait)
    issue_V(0);  CP_COMMIT();                 // G2 (non-T: safe pre-wait)
    asm volatile("griddepcontrol.wait;" ::: "memory");   // transpose done
    issue_AB(1); issue_V(1); CP_COMMIT();     // G3 (T planes)

    float acc[8][4];
    #pragma unroll
    for (int ni = 0; ni < 8; ni++)
        #pragma unroll
        for (int k = 0; k < 4; k++) acc[ni][k] = 0.0f;

    for (int phase = 0; phase < 2; phase++) {
        const uint32_t sA_u = smb + (phase ? AT_A1 : AT_A0);
        const uint32_t sB_u = smb + (phase ? AT_B1 : AT_B0);
        const uint32_t sV_u = smb + (phase ? AT_V1 : AT_V0);
        if (phase == 0) { CP_WAIT2(); } else { CP_WAIT1(); }
        __syncthreads();

        // ---- energy mma ----
        float ef[4][4][4];
        #pragma unroll
        for (int mi = 0; mi < 4; mi++)
            #pragma unroll
            for (int ni = 0; ni < 4; ni++)
                #pragma unroll
                for (int k = 0; k < 4; k++) ef[mi][ni][k] = 0.0f;
        #pragma unroll
        for (int ks = 0; ks < 2; ks++) {
            uint32_t af[4][4];
            #pragma unroll
            for (int mi = 0; mi < 4; mi++) {
                int row = ks * 16 + tr_row_a;
                int col = em * 64 + mi * 16 + tr_col_a;
                ldmatrix_x4_trans(af[mi][0], af[mi][1], af[mi][2], af[mi][3],
                                  sA_u + sw256((uint32_t)(row * 256 + col * 2)));
            }
            uint32_t bfr[2][4];
            #pragma unroll
            for (int n16 = 0; n16 < 2; n16++) {
                int row = ks * 16 + tr_row_b;
                int col = en * 32 + n16 * 16 + tr_col_b;
                ldmatrix_x4_trans(bfr[n16][0], bfr[n16][1], bfr[n16][2], bfr[n16][3],
                                  sB_u + sw256((uint32_t)(row * 256 + col * 2)));
            }
            #pragma unroll
            for (int mi = 0; mi < 4; mi++)
                #pragma unroll
                for (int ni = 0; ni < 4; ni++)
                    mma_bf16(ef[mi][ni][0], ef[mi][ni][1], ef[mi][ni][2], ef[mi][ni][3],
                             af[mi][0], af[mi][1], af[mi][2], af[mi][3],
                             bfr[ni >> 1][(ni & 1) * 2 + 0], bfr[ni >> 1][(ni & 1) * 2 + 1]);
        }

        // ---- exp in registers + per-j column sums ----
        float psum[4][2];
        #pragma unroll
        for (int ni = 0; ni < 4; ni++) { psum[ni][0] = 0.0f; psum[ni][1] = 0.0f; }
        #pragma unroll
        for (int mi = 0; mi < 4; mi++)
            #pragma unroll
            for (int ni = 0; ni < 4; ni++) {
                ef[mi][ni][0] = __expf(ef[mi][ni][0]);
                ef[mi][ni][1] = __expf(ef[mi][ni][1]);
                ef[mi][ni][2] = __expf(ef[mi][ni][2]);
                ef[mi][ni][3] = __expf(ef[mi][ni][3]);
                psum[ni][0] += ef[mi][ni][0] + ef[mi][ni][2];
                psum[ni][1] += ef[mi][ni][1] + ef[mi][ni][3];
            }
        #pragma unroll
        for (int ni = 0; ni < 4; ni++) {
            #pragma unroll
            for (int d = 4; d <= 16; d <<= 1) {
                psum[ni][0] += __shfl_xor_sync(0xffffffffu, psum[ni][0], d);
                psum[ni][1] += __shfl_xor_sync(0xffffffffu, psum[ni][1], d);
            }
        }
        if ((lane >> 2) == 0) {
            #pragma unroll
            for (int ni = 0; ni < 4; ni++) {
                int j0 = en * 32 + ni * 8 + (lane & 3) * 2;
                *(float2*)&ssum[em * 128 + j0] = make_float2(psum[ni][0], psum[ni][1]);
            }
        }
        __syncthreads();

        // ---- normalize + store P fp16 [g][j] ----
        #pragma unroll
        for (int ni = 0; ni < 4; ni++) {
            int j0 = en * 32 + ni * 8 + (lane & 3) * 2;
            float2 sa = *(float2*)&ssum[j0];
            float2 sb = *(float2*)&ssum[128 + j0];
            float is0 = 1.0f / (sa.x + sb.x);
            float is1 = 1.0f / (sa.y + sb.y);
            #pragma unroll
            for (int mi = 0; mi < 4; mi++) {
                int g0 = em * 64 + mi * 16 + (lane >> 2);
                __half2 p0 = __floats2half2_rn(ef[mi][ni][0] * is0, ef[mi][ni][1] * is1);
                __half2 p1 = __floats2half2_rn(ef[mi][ni][2] * is0, ef[mi][ni][3] * is1);
                *(uint32_t*)(smem + AT_P + sw256((uint32_t)(g0 * 256 + j0 * 2)))       = *(uint32_t*)&p0;
                *(uint32_t*)(smem + AT_P + sw256((uint32_t)((g0 + 8) * 256 + j0 * 2))) = *(uint32_t*)&p1;
            }
        }
        if (phase == 0) CP_WAIT1();   // V0 arrived (G2)
        __syncthreads();

        // ---- O mma: A = P (m=j, k=g, trans), B = V (n=c, k=g) ----
        {
            #pragma unroll
            for (int ks = 0; ks < 8; ks++) {
                uint32_t af[4];
                {
                    int row = ks * 16 + tr_row_a;
                    int col = wid * 16 + tr_col_a;
                    ldmatrix_x4_trans(af[0], af[1], af[2], af[3],
                                      sP_u + sw256((uint32_t)(row * 256 + col * 2)));
                }
                uint32_t bfr[4][4];
                #pragma unroll
                for (int n16 = 0; n16 < 4; n16++) {
                    int row = n16 * 16 + b_row_in;
                    ldmatrix_x4(bfr[n16][0], bfr[n16][1], bfr[n16][2], bfr[n16][3],
                                sV_u + sw256((uint32_t)(row * 256 + ks * 32) + (uint32_t)b_kseg));
                }
                #pragma unroll
                for (int n16 = 0; n16 < 4; n16++)
                    #pragma unroll
                    for (int sub = 0; sub < 2; sub++)
                        mma_f16(acc[n16 * 2 + sub][0], acc[n16 * 2 + sub][1],
                                acc[n16 * 2 + sub][2], acc[n16 * 2 + sub][3],
                                af[0], af[1], af[2], af[3],
                                bfr[n16][sub * 2 + 0], bfr[n16][sub * 2 + 1]);
            }
        }
        if (phase == 1) CP_WAIT0();   // x tile arrived (G4)
        __syncthreads();

        if (phase == 0) {
            // prefetch epilogue x tile (64ch x 128j fp32) into dead V0/A0/B0
            #pragma unroll
            for (int it = 0; it < 8; it++) {
                int idx = tid + it * 256;
                int c = idx >> 5, jseg = idx & 31;
                const char* gsrc = (const char*)(x + ((size_t)(vc0 + c) * HH + i) * WW)
                                   + jseg * 16;
                uint32_t dstoff = (c < 32) ? (uint32_t)(AT_V0 + c * 512)
                                : (c < 48) ? (uint32_t)(AT_A0 + (c - 32) * 512)
                                           : (uint32_t)(AT_B0 + (c - 48) * 512);
                CP_ASYNC16(smb + dstoff + jseg * 16, gsrc);
            }
            CP_COMMIT();              // G4
        }
    }

    // ---- epilogue: x from smem staging ----
    const float gm = gamma[0];
    const int jb = wid * 16 + (lane >> 2);
    #pragma unroll
    for (int ni = 0; ni < 8; ni++) {
        int c0 = ni * 8 + (lane & 3) * 2;
        uint32_t xbase = (ni < 4) ? (uint32_t)(AT_V0 + c0 * 512)
                      : (ni < 6) ? (uint32_t)(AT_A0 + (c0 - 32) * 512)
                                 : (uint32_t)(AT_B0 + (c0 - 48) * 512);
        #pragma unroll
        for (int hf = 0; hf < 2; hf++) {
            int j = jb + hf * 8;
            size_t off0 = (((size_t)vc0 + c0) * HH + i) * WW + j;
            size_t off1 = off0 + HWS;
            float x0 = *(const float*)(smem + xbase + j * 4);
            float x1 = *(const float*)(smem + xbase + 512 + j * 4);
            out[off0] = gm * acc[ni][hf * 2 + 0] + x0;
            out[off1] = gm * acc[ni][hf * 2 + 1] + x1;
        }
    }
}

// ---------------------------------------------------------------------------
extern "C" void kernel_launch(void* const* d_in, const int* in_sizes, int n_in,
                              void* d_out, int out_size)
{
    const float* x     = (const float*)d_in[0];
    const float* Wq    = (const float*)d_in[1];
    const float* bq    = (const float*)d_in[2];
    const float* Wk    = (const float*)d_in[3];
    const float* bk    = (const float*)d_in[4];
    const float* Wv    = (const float*)d_in[5];
    const float* bv    = (const float*)d_in[6];
    const float* gamma = (const float*)d_in[7];
    float* out = (float*)d_out;

    cudaFuncSetAttribute(attn_kernel, cudaFuncAttributeMaxDynamicSharedMemorySize,
                         AT_SMEM);
    cudaFuncSetAttribute(proj_mma_kernel, cudaFuncAttributeMaxDynamicSharedMemorySize,
                         65536);

    prep_w_kernel<<<384, 256>>>(Wq, Wk, Wv);
    prep_x_kernel<<<dim3(256, 4, NB), 256>>>(x);
    proj_mma_kernel<<<dim3(3, 128, NB), 256, 65536>>>(bq, bk, bv);
    transpose_kernel<<<dim3(2, 2, 1536), 256>>>();

    // attn via PDL: launches while transpose runs; gates T reads in-kernel.
    cudaLaunchConfig_t cfg = {};
    cfg.gridDim = dim3(HH, NB * 4, 1);
    cfg.blockDim = dim3(256, 1, 1);
    cfg.dynamicSmemBytes = AT_SMEM;
    cfg.stream = 0;
    cudaLaunchAttribute attrs[1];
    attrs[0].id = cudaLaunchAttributeProgrammaticStreamSerialization;
    attrs[0].val.programmaticStreamSerializationAllowed = 1;
    cfg.attrs = attrs;
    cfg.numAttrs = 1;
    cudaLaunchKernelEx(&cfg, attn_kernel, x, gamma, out);
}

// round 16
// speedup vs baseline: 1.0657x; 1.0020x over previous
#include <cuda_runtime.h>
#include <cuda_bf16.h>
#include <cuda_fp16.h>
#include <cstdint>

#define HH 128
#define WW 128
#define HWS 16384
#define NB 4
#define KP 512   // split-K storage: [hi(256) | lo(256)]; 12 virtual chunks at GEMM

// ---------------- scratch (device globals; allocation-free rule) ------------
__device__ __align__(16) __nv_bfloat16 g_qhi[(size_t)NB * 32 * HWS];
__device__ __align__(16) __nv_bfloat16 g_qlo[(size_t)NB * 32 * HWS];
__device__ __align__(16) __nv_bfloat16 g_khi[(size_t)NB * 32 * HWS];
__device__ __align__(16) __nv_bfloat16 g_klo[(size_t)NB * 32 * HWS];
__device__ __align__(16) __nv_bfloat16 g_qhiT[(size_t)NB * 32 * HWS];
__device__ __align__(16) __nv_bfloat16 g_qloT[(size_t)NB * 32 * HWS];
__device__ __align__(16) __nv_bfloat16 g_khiT[(size_t)NB * 32 * HWS];
__device__ __align__(16) __nv_bfloat16 g_kloT[(size_t)NB * 32 * HWS];
__device__ __align__(16) __half g_v [(size_t)NB * 256 * HWS];
__device__ __align__(16) __half g_vT[(size_t)NB * 256 * HWS];
__device__ __align__(16) __nv_bfloat16 g_wsplit[(size_t)384 * KP];       // [m][hi|lo]
__device__ __align__(16) __nv_bfloat16 g_xt[(size_t)NB * HWS * KP];      // [b][p][hi|lo]

// single TU-wide dynamic smem symbol (char; cast per-kernel)
extern __shared__ __align__(1024) char smem_raw[];

static __device__ __forceinline__ uint32_t sw128(uint32_t off) {
    return off ^ ((off >> 3) & 0x70);
}
static __device__ __forceinline__ uint32_t sw256(uint32_t off) {
    return off ^ (((off >> 8) & 7) << 4);
}
__device__ __forceinline__ uint32_t smem_u32(const void* p) {
    uint32_t a;
    asm("{ .reg .u64 t; cvta.to.shared.u64 t, %1; cvt.u32.u64 %0, t; }"
        : "=r"(a) : "l"(p));
    return a;
}
__device__ __forceinline__ void ldmatrix_x4(uint32_t& r0, uint32_t& r1,
                                            uint32_t& r2, uint32_t& r3, uint32_t addr) {
    asm volatile("ldmatrix.sync.aligned.m8n8.x4.shared.b16 {%0,%1,%2,%3}, [%4];"
                 : "=r"(r0), "=r"(r1), "=r"(r2), "=r"(r3) : "r"(addr));
}
__device__ __forceinline__ void ldmatrix_x4_trans(uint32_t& r0, uint32_t& r1,
                                                  uint32_t& r2, uint32_t& r3, uint32_t addr) {
    asm volatile("ldmatrix.sync.aligned.m8n8.x4.trans.shared.b16 {%0,%1,%2,%3}, [%4];"
                 : "=r"(r0), "=r"(r1), "=r"(r2), "=r"(r3) : "r"(addr));
}
__device__ __forceinline__ void mma_bf16(float& d0, float& d1, float& d2, float& d3,
                                         uint32_t a0, uint32_t a1, uint32_t a2, uint32_t a3,
                                         uint32_t b0, uint32_t b1) {
    asm volatile("mma.sync.aligned.m16n8k16.row.col.f32.bf16.bf16.f32 "
                 "{%0,%1,%2,%3}, {%4,%5,%6,%7}, {%8,%9}, {%0,%1,%2,%3};"
                 : "+f"(d0), "+f"(d1), "+f"(d2), "+f"(d3)
                 : "r"(a0), "r"(a1), "r"(a2), "r"(a3), "r"(b0), "r"(b1));
}
__device__ __forceinline__ void mma_f16(float& d0, float& d1, float& d2, float& d3,
                                        uint32_t a0, uint32_t a1, uint32_t a2, uint32_t a3,
                                        uint32_t b0, uint32_t b1) {
    asm volatile("mma.sync.aligned.m16n8k16.row.col.f32.f16.f16.f32 "
                 "{%0,%1,%2,%3}, {%4,%5,%6,%7}, {%8,%9}, {%0,%1,%2,%3};"
                 : "+f"(d0), "+f"(d1), "+f"(d2), "+f"(d3)
                 : "r"(a0), "r"(a1), "r"(a2), "r"(a3), "r"(b0), "r"(b1));
}
#define CP_ASYNC16(dst, src) \
    asm volatile("cp.async.cg.shared.global [%0], [%1], 16;" :: "r"(dst), "l"(src))
#define CP_COMMIT() asm volatile("cp.async.commit_group;" ::: "memory")
#define CP_WAIT2()  asm volatile("cp.async.wait_group 2;" ::: "memory")
#define CP_WAIT1()  asm volatile("cp.async.wait_group 1;" ::: "memory")
#define CP_WAIT0()  asm volatile("cp.async.wait_group 0;" ::: "memory")
#define GDC_LAUNCH() asm volatile("griddepcontrol.launch_dependents;")
#define GDC_WAIT()   asm volatile("griddepcontrol.wait;" ::: "memory")

// ---------------------------------------------------------------------------
// prep_w: W' bf16 [384][512]; rows 0-255 Wv, 256-287 Wq, 288-319 Wk, 320-383 0
// ---------------------------------------------------------------------------
__global__ void prep_w_kernel(const float* __restrict__ Wq, const float* __restrict__ Wk,
                              const float* __restrict__ Wv)
{
    const int m = blockIdx.x;
    const int c = threadIdx.x;
    float w = 0.0f;
    if (m < 256)      w = Wv[m * 256 + c];
    else if (m < 288) w = Wq[(m - 256) * 256 + c];
    else if (m < 320) w = Wk[(m - 288) * 256 + c];
    __nv_bfloat16 hi = __float2bfloat16(w);
    __nv_bfloat16 lo = __float2bfloat16(w - __bfloat162float(hi));
    g_wsplit[(size_t)m * KP + c]       = hi;
    g_wsplit[(size_t)m * KP + 256 + c] = lo;
}

// ---------------------------------------------------------------------------
// prep_x: XT' bf16 [b][p][512]. Signals dependents at top: proj (PDL) may
// launch and do setup; proj gates its global reads on our completion.
// ---------------------------------------------------------------------------
__global__ void prep_x_kernel(const float* __restrict__ x)
{
    GDC_LAUNCH();
    __shared__ float sm[64][65];
    const int b = blockIdx.z, ct = blockIdx.y, pt = blockIdx.x;
    const int c0 = ct * 64, p0 = pt * 64;
    const int t = threadIdx.x;
    const int pj = t & 63, ci0 = t >> 6;
    const float* xb = x + ((size_t)b * 256 + c0) * HWS + p0;
    #pragma unroll
    for (int i = 0; i < 16; i++) {
        int ci = ci0 + i * 4;
        sm[ci][pj] = xb[(size_t)ci * HWS + pj];
    }
    __syncthreads();
    const int cp = t & 31, pl = t >> 5;
    #pragma unroll
    for (int i = 0; i < 8; i++) {
        int p = pl + i * 8;
        float f0 = sm[2 * cp][p], f1 = sm[2 * cp + 1][p];
        __nv_bfloat16 h0 = __float2bfloat16(f0), h1 = __float2bfloat16(f1);
        __nv_bfloat16 l0 = __float2bfloat16(f0 - __bfloat162float(h0));
        __nv_bfloat16 l1 = __float2bfloat16(f1 - __bfloat162float(h1));
        __nv_bfloat162 hp; hp.x = h0; hp.y = h1;
        __nv_bfloat162 lp; lp.x = l0; lp.y = l1;
        __nv_bfloat16* row = g_xt + ((size_t)b * HWS + p0 + p) * KP;
        *(__nv_bfloat162*)(row + c0 + 2 * cp)       = hp;
        *(__nv_bfloat162*)(row + 256 + c0 + 2 * cp) = lp;
    }
}

// ---------------------------------------------------------------------------
// proj_mma: 2-stage cp.async double-buffered bf16 mma GEMM; mt fastest.
// PDL: launched during prep_x; signals transpose at top (transpose waits for
// our completion itself); gates own global reads on prep_x completion.
// ---------------------------------------------------------------------------
__constant__ int ACH[12] = {0, 1, 2, 3, 0, 1, 2, 3, 4, 5, 6, 7};
__constant__ int BCH[12] = {0, 1, 2, 3, 4, 5, 6, 7, 0, 1, 2, 3};

__global__ void __launch_bounds__(256) proj_mma_kernel(
    const float* __restrict__ bq, const float* __restrict__ bk,
    const float* __restrict__ bv)
{
    GDC_LAUNCH();
    char* smem = smem_raw;
    const uint32_t smem_base = smem_u32(smem);
    const int tid = threadIdx.x;
    const int wid = tid >> 5, lane = tid & 31;
    const int warp_m = wid & 1;
    const int warp_n = wid >> 1;
    const int mt = blockIdx.x, pt = blockIdx.y, b = blockIdx.z;
    const bool mma_active = (mt < 2) || (warp_m == 0);

    const char* Abase = (const char*)(g_wsplit + (size_t)mt * 128 * KP);
    const char* Bbase = (const char*)(g_xt + ((size_t)b * HWS + pt * 128) * KP);

    float acc[4][4][4];
    #pragma unroll
    for (int i = 0; i < 4; i++)
        #pragma unroll
        for (int j = 0; j < 4; j++)
            #pragma unroll
            for (int k = 0; k < 4; k++) acc[i][j][k] = 0.0f;

    const int a_row_in = lane & 15;
    const int a_kseg   = (lane >> 4) << 4;
    const int b_row_in = (lane & 7) + ((lane >> 4) << 3);
    const int b_kseg   = ((lane >> 3) & 1) << 4;

    const int ld_row = tid >> 3, ld_seg = tid & 7;

    auto issue = [&](int ch, int st) {
        const size_t a0b = (size_t)ACH[ch] * 128;
        const size_t b0b = (size_t)BCH[ch] * 128;
        const uint32_t sb = smem_base + st * 32768;
        #pragma unroll
        for (int r = 0; r < 4; r++) {
            int row = ld_row + r * 32;
            uint32_t so = sw128((uint32_t)(row * 128 + ld_seg * 16));
            CP_ASYNC16(sb + so,         Abase + (size_t)row * (KP * 2) + a0b + ld_seg * 16);
            CP_ASYNC16(sb + 16384 + so, Bbase + (size_t)row * (KP * 2) + b0b + ld_seg * 16);
        }
    };

    GDC_WAIT();   // g_xt (prep_x) ready; g_wsplit (prep_w) transitively ready
    issue(0, 0);
    CP_COMMIT();

    for (int ch = 0; ch < 12; ch++) {
        const int st = ch & 1;
        if (ch + 1 < 12) issue(ch + 1, st ^ 1);
        CP_COMMIT();
        CP_WAIT1();
        __syncthreads();

        if (mma_active) {
            const uint32_t sA_u = smem_base + st * 32768;
            const uint32_t sB_u = sA_u + 16384;
            #pragma unroll
            for (int kk = 0; kk < 4; kk++) {
                uint32_t af[4][4];
                #pragma unroll
                for (int mi = 0; mi < 4; mi++) {
                    int row = warp_m * 64 + mi * 16 + a_row_in;
                    ldmatrix_x4(af[mi][0], af[mi][1], af[mi][2], af[mi][3],
                                sA_u + sw128((uint32_t)(row * 128 + kk * 32 + a_kseg)));
                }
                uint32_t bf[2][4];
                #pragma unroll
                for (int ni16 = 0; ni16 < 2; ni16++) {
                    int row = warp_n * 32 + ni16 * 16 + b_row_in;
                    ldmatrix_x4(bf[ni16][0], bf[ni16][1], bf[ni16][2], bf[ni16][3],
                                sB_u + sw128((uint32_t)(row * 128 + kk * 32 + b_kseg)));
                }
                #pragma unroll
                for (int mi = 0; mi < 4; mi++)
                    #pragma unroll
                    for (int ni = 0; ni < 4; ni++)
                        mma_bf16(acc[mi][ni][0], acc[mi][ni][1], acc[mi][ni][2], acc[mi][ni][3],
                                 af[mi][0], af[mi][1], af[mi][2], af[mi][3],
                                 bf[ni >> 1][(ni & 1) * 2 + 0], bf[ni >> 1][(ni & 1) * 2 + 1]);
            }
        }
        __syncthreads();
    }

    const int p0 = pt * 128 + warp_n * 32 + 2 * (lane & 3);
    #pragma unroll
    for (int mi = 0; mi < 4; mi++) {
        #pragma unroll
        for (int half = 0; half < 2; half++) {
            int m = mt * 128 + warp_m * 64 + mi * 16 + (lane >> 2) + half * 8;
            #pragma unroll
            for (int ni = 0; ni < 4; ni++) {
                float v0 = acc[mi][ni][half * 2 + 0];
                float v1 = acc[mi][ni][half * 2 + 1];
                int p = p0 + ni * 8;
                if (m < 256) {
                    float bias = bv[m];
                    __half2 hv = __floats2half2_rn(v0 + bias, v1 + bias);
                    *(__half2*)&g_v[((size_t)b * 256 + m) * HWS + p] = hv;
                } else if (m < 320) {
                    const bool isq = (m < 288);
                    int c = isq ? (m - 256) : (m - 288);
                    float bias = isq ? bq[c] : bk[c];
                    float f0 = v0 + bias, f1 = v1 + bias;
                    __nv_bfloat16 h0 = __float2bfloat16(f0), h1 = __float2bfloat16(f1);
                    __nv_bfloat16 l0 = __float2bfloat16(f0 - __bfloat162float(h0));
                    __nv_bfloat16 l1 = __float2bfloat16(f1 - __bfloat162float(h1));
                    __nv_bfloat162 hp; hp.x = h0; hp.y = h1;
                    __nv_bfloat162 lp; lp.x = l0; lp.y = l1;
                    size_t off = ((size_t)b * 32 + c) * HWS + p;
                    if (isq) {
                        *(__nv_bfloat162*)&g_qhi[off] = hp;
                        *(__nv_bfloat162*)&g_qlo[off] = lp;
                    } else {
                        *(__nv_bfloat162*)&g_khi[off] = hp;
                        *(__nv_bfloat162*)&g_klo[off] = lp;
                    }
                }
            }
        }
    }
}

// ---------------------------------------------------------------------------
// transpose: PDL-launched during proj. ORDER MATTERS: wait for proj's
// completion FIRST, then signal attn (so attn's pre-wait reads of proj
// outputs are safe), then do the transpose work.
// ---------------------------------------------------------------------------
__global__ void transpose_kernel()
{
    GDC_WAIT();     // proj outputs complete
    GDC_LAUNCH();   // attn may launch now (its G1/G2 only touch proj outputs)
    __shared__ uint16_t sm[64][70];
    const int plane = blockIdx.z;
    const uint16_t* src;
    uint16_t* dst;
    if (plane < 512) {
        int t = plane >> 7, ch = plane & 127;
        const __nv_bfloat16* s;
        __nv_bfloat16* d;
        switch (t) {
            case 0:  s = g_qhi; d = g_qhiT; break;
            case 1:  s = g_qlo; d = g_qloT; break;
            case 2:  s = g_khi; d = g_khiT; break;
            default: s = g_klo; d = g_kloT; break;
        }
        src = (const uint16_t*)(s + (size_t)ch * HWS);
        dst = (uint16_t*)(d + (size_t)ch * HWS);
    } else {
        int ch = plane - 512;
        src = (const uint16_t*)(g_v + (size_t)ch * HWS);
        dst = (uint16_t*)(g_vT + (size_t)ch * HWS);
    }
    const int ti = blockIdx.y * 64, tj = blockIdx.x * 64;
    const int t = threadIdx.x;
    const int cw = (t & 31) * 2, r0 = t >> 5;
    #pragma unroll
    for (int p = 0; p < 8; p++) {
        int r = r0 + p * 8;
        *(uint32_t*)&sm[r][cw] = *(const uint32_t*)&src[(size_t)(ti + r) * WW + tj + cw];
    }
    __syncthreads();
    const int ch2 = (t & 31) * 2, w0 = t >> 5;
    #pragma unroll
    for (int p = 0; p < 8; p++) {
        int w = w0 + p * 8;
        uint32_t v = (uint32_t)sm[ch2][w] | ((uint32_t)sm[ch2 + 1][w] << 16);
        *(uint32_t*)&dst[(size_t)(tj + w) * HH + ti + ch2] = v;
    }
}

// ---------------------------------------------------------------------------
// Tensor-core criss-cross attention. PDL: launches while transpose runs
// (after transpose's wait => proj complete); G1/G2 issue immediately;
// griddepcontrol.wait gates only G3 (T-plane reads).
// ---------------------------------------------------------------------------
#define AT_P    0
#define AT_V0   32768
#define AT_V1   49152
#define AT_A0   65536
#define AT_A1   73728
#define AT_B0   81920
#define AT_B1   90112
#define AT_SSUM 98304
#define AT_SMEM (98304 + 1024)

__global__ void __launch_bounds__(256, 2) attn_kernel(
    const float* __restrict__ x, const float* __restrict__ gamma,
    float* __restrict__ out)
{
    char* smem = smem_raw;
    float* ssum = (float*)(smem + AT_SSUM);

    const int i  = blockIdx.x;
    const int bh = blockIdx.y;
    const int b = bh >> 2, h = bh & 3;
    const int tid = threadIdx.x;
    const int wid = tid >> 5, lane = tid & 31;

    const uint32_t smb  = smem_u32(smem);
    const uint32_t sP_u = smb + AT_P;

    const int b_row_in = (lane & 7) + ((lane >> 4) << 3);
    const int b_kseg   = ((lane >> 3) & 1) << 4;
    const int tr_row_a = (lane & 7) + (((lane >> 4) & 1) << 3);
    const int tr_col_a = ((lane >> 3) & 1) << 3;
    const int tr_row_b = (lane & 7) + (((lane >> 3) & 1) << 3);
    const int tr_col_b = ((lane >> 4) & 1) << 3;

    const int em = wid & 1, en = wid >> 1;

    const int qkc0 = (b * 32 + h * 8);
    const int vc0  = (b * 256 + h * 64);
    const int loff = i * 128;

    // zero pad rows 24-31 of A0/A1/B0/B1 (persist across phases)
    #pragma unroll
    for (int z = 0; z < 2; z++) {
        int idx = tid + z * 256;
        int bufsel = idx >> 7;
        int r = 24 + ((idx >> 4) & 7), chunk = idx & 15;
        uint32_t base = (bufsel == 0) ? AT_A0 : (bufsel == 1) ? AT_A1
                       : (bufsel == 2) ? AT_B0 : AT_B1;
        *(uint4*)(smem + base + sw256((uint32_t)(r * 256 + chunk * 16))) =
            make_uint4(0, 0, 0, 0);
    }

    auto issue_AB = [&](int ph) {
        const __nv_bfloat16* Khi = ph ? g_khiT : g_khi;
        const __nv_bfloat16* Klo = ph ? g_kloT : g_klo;
        const __nv_bfloat16* Qhi = ph ? g_qhiT : g_qhi;
        const __nv_bfloat16* Qlo = ph ? g_qloT : g_qlo;
        const uint32_t aU = smb + (ph ? AT_A1 : AT_A0);
        const uint32_t bU = smb + (ph ? AT_B1 : AT_B0);
        #pragma unroll
        for (int it = 0; it < 3; it++) {
            int idx = tid + it * 256;
            int rr2 = idx >> 4, chunk = idx & 15;
            int tile = rr2 >= 24;
            int r = tile ? (rr2 - 24) : rr2;
            int c = r & 7;
            const __nv_bfloat16* src;
            if (!tile) src = (r < 16) ? Khi : Klo;
            else       src = (r >= 8 && r < 16) ? Qlo : Qhi;
            const char* gsrc = (const char*)(src + (size_t)(qkc0 + c) * HWS + loff) + chunk * 16;
            uint32_t dst = (tile ? bU : aU) + sw256((uint32_t)(r * 256 + chunk * 16));
            CP_ASYNC16(dst, gsrc);
        }
    };
    auto issue_V = [&](int ph) {
        const __half* Vp = ph ? g_vT : g_v;
        const uint32_t vU = smb + (ph ? AT_V1 : AT_V0);
        #pragma unroll
        for (int it = 0; it < 4; it++) {
            int idx = tid + it * 256;
            int c = idx >> 4, chunk = idx & 15;
            const char* gsrc = (const char*)(Vp + (size_t)(vc0 + c) * HWS + loff) + chunk * 16;
            CP_ASYNC16(vU + sw256((uint32_t)(c * 256 + chunk * 16)), gsrc);
        }
    };

    issue_AB(0); CP_COMMIT();                 // G1 (non-T: safe pre-wait)
    issue_V(0);  CP_COMMIT();                 // G2 (non-T: safe pre-wait)
    GDC_WAIT();                               // transpose done
    issue_AB(1); issue_V(1); CP_COMMIT();     // G3 (T planes)

    float acc[8][4];
    #pragma unroll
    for (int ni = 0; ni < 8; ni++)
        #pragma unroll
        for (int k = 0; k < 4; k++) acc[ni][k] = 0.0f;

    for (int phase = 0; phase < 2; phase++) {
        const uint32_t sA_u = smb + (phase ? AT_A1 : AT_A0);
        const uint32_t sB_u = smb + (phase ? AT_B1 : AT_B0);
        const uint32_t sV_u = smb + (phase ? AT_V1 : AT_V0);
        if (phase == 0) { CP_WAIT2(); } else { CP_WAIT1(); }
        __syncthreads();

        // ---- energy mma ----
        float ef[4][4][4];
        #pragma unroll
        for (int mi = 0; mi < 4; mi++)
            #pragma unroll
            for (int ni = 0; ni < 4; ni++)
                #pragma unroll
                for (int k = 0; k < 4; k++) ef[mi][ni][k] = 0.0f;
        #pragma unroll
        for (int ks = 0; ks < 2; ks++) {
            uint32_t af[4][4];
            #pragma unroll
            for (int mi = 0; mi < 4; mi++) {
                int row = ks * 16 + tr_row_a;
                int col = em * 64 + mi * 16 + tr_col_a;
                ldmatrix_x4_trans(af[mi][0], af[mi][1], af[mi][2], af[mi][3],
                                  sA_u + sw256((uint32_t)(row * 256 + col * 2)));
            }
            uint32_t bfr[2][4];
            #pragma unroll
            for (int n16 = 0; n16 < 2; n16++) {
                int row = ks * 16 + tr_row_b;
                int col = en * 32 + n16 * 16 + tr_col_b;
                ldmatrix_x4_trans(bfr[n16][0], bfr[n16][1], bfr[n16][2], bfr[n16][3],
                                  sB_u + sw256((uint32_t)(row * 256 + col * 2)));
            }
            #pragma unroll
            for (int mi = 0; mi < 4; mi++)
                #pragma unroll
                for (int ni = 0; ni < 4; ni++)
                    mma_bf16(ef[mi][ni][0], ef[mi][ni][1], ef[mi][ni][2], ef[mi][ni][3],
                             af[mi][0], af[mi][1], af[mi][2], af[mi][3],
                             bfr[ni >> 1][(ni & 1) * 2 + 0], bfr[ni >> 1][(ni & 1) * 2 + 1]);
        }

        // ---- exp in registers + per-j column sums ----
        float psum[4][2];
        #pragma unroll
        for (int ni = 0; ni < 4; ni++) { psum[ni][0] = 0.0f; psum[ni][1] = 0.0f; }
        #pragma unroll
        for (int mi = 0; mi < 4; mi++)
            #pragma unroll
            for (int ni = 0; ni < 4; ni++) {
                ef[mi][ni][0] = __expf(ef[mi][ni][0]);
                ef[mi][ni][1] = __expf(ef[mi][ni][1]);
                ef[mi][ni][2] = __expf(ef[mi][ni][2]);
                ef[mi][ni][3] = __expf(ef[mi][ni][3]);
                psum[ni][0] += ef[mi][ni][0] + ef[mi][ni][2];
                psum[ni][1] += ef[mi][ni][1] + ef[mi][ni][3];
            }
        #pragma unroll
        for (int ni = 0; ni < 4; ni++) {
            #pragma unroll
            for (int d = 4; d <= 16; d <<= 1) {
                psum[ni][0] += __shfl_xor_sync(0xffffffffu, psum[ni][0], d);
                psum[ni][1] += __shfl_xor_sync(0xffffffffu, psum[ni][1], d);
            }
        }
        if ((lane >> 2) == 0) {
            #pragma unroll
            for (int ni = 0; ni < 4; ni++) {
                int j0 = en * 32 + ni * 8 + (lane & 3) * 2;
                *(float2*)&ssum[em * 128 + j0] = make_float2(psum[ni][0], psum[ni][1]);
            }
        }
        __syncthreads();

        // ---- normalize + store P fp16 [g][j] ----
        #pragma unroll
        for (int ni = 0; ni < 4; ni++) {
            int j0 = en * 32 + ni * 8 + (lane & 3) * 2;
            float2 sa = *(float2*)&ssum[j0];
            float2 sb = *(float2*)&ssum[128 + j0];
            float is0 = 1.0f / (sa.x + sb.x);
            float is1 = 1.0f / (sa.y + sb.y);
            #pragma unroll
            for (int mi = 0; mi < 4; mi++) {
                int g0 = em * 64 + mi * 16 + (lane >> 2);
                __half2 p0 = __floats2half2_rn(ef[mi][ni][0] * is0, ef[mi][ni][1] * is1);
                __half2 p1 = __floats2half2_rn(ef[mi][ni][2] * is0, ef[mi][ni][3] * is1);
                *(uint32_t*)(smem + AT_P + sw256((uint32_t)(g0 * 256 + j0 * 2)))       = *(uint32_t*)&p0;
                *(uint32_t*)(smem + AT_P + sw256((uint32_t)((g0 + 8) * 256 + j0 * 2))) = *(uint32_t*)&p1;
            }
        }
        if (phase == 0) CP_WAIT1();   // V0 arrived (G2)
        __syncthreads();

        // ---- O mma: A = P (m=j, k=g, trans), B = V (n=c, k=g) ----
        {
            #pragma unroll
            for (int ks = 0; ks < 8; ks++) {
                uint32_t af[4];
                {
                    int row = ks * 16 + tr_row_a;
                    int col = wid * 16 + tr_col_a;
                    ldmatrix_x4_trans(af[0], af[1], af[2], af[3],
                                      sP_u + sw256((uint32_t)(row * 256 + col * 2)));
                }
                uint32_t bfr[4][4];
                #pragma unroll
                for (int n16 = 0; n16 < 4; n16++) {
                    int row = n16 * 16 + b_row_in;
                    ldmatrix_x4(bfr[n16][0], bfr[n16][1], bfr[n16][2], bfr[n16][3],
                                sV_u + sw256((uint32_t)(row * 256 + ks * 32) + (uint32_t)b_kseg));
                }
                #pragma unroll
                for (int n16 = 0; n16 < 4; n16++)
                    #pragma unroll
                    for (int sub = 0; sub < 2; sub++)
                        mma_f16(acc[n16 * 2 + sub][0], acc[n16 * 2 + sub][1],
                                acc[n16 * 2 + sub][2], acc[n16 * 2 + sub][3],
                                af[0], af[1], af[2], af[3],
                                bfr[n16][sub * 2 + 0], bfr[n16][sub * 2 + 1]);
            }
        }
        if (phase == 1) CP_WAIT0();   // x tile arrived (G4)
        __syncthreads();

        if (phase == 0) {
            // prefetch epilogue x tile (64ch x 128j fp32) into dead V0/A0/B0
            #pragma unroll
            for (int it = 0; it < 8; it++) {
                int idx = tid + it * 256;
                int c = idx >> 5, jseg = idx & 31;
                const char* gsrc = (const char*)(x + ((size_t)(vc0 + c) * HH + i) * WW)
                                   + jseg * 16;
                uint32_t dstoff = (c < 32) ? (uint32_t)(AT_V0 + c * 512)
                                : (c < 48) ? (uint32_t)(AT_A0 + (c - 32) * 512)
                                           : (uint32_t)(AT_B0 + (c - 48) * 512);
                CP_ASYNC16(smb + dstoff + jseg * 16, gsrc);
            }
            CP_COMMIT();              // G4
        }
    }

    // ---- epilogue: x from smem staging ----
    const float gm = gamma[0];
    const int jb = wid * 16 + (lane >> 2);
    #pragma unroll
    for (int ni = 0; ni < 8; ni++) {
        int c0 = ni * 8 + (lane & 3) * 2;
        uint32_t xbase = (ni < 4) ? (uint32_t)(AT_V0 + c0 * 512)
                      : (ni < 6) ? (uint32_t)(AT_A0 + (c0 - 32) * 512)
                                 : (uint32_t)(AT_B0 + (c0 - 48) * 512);
        #pragma unroll
        for (int hf = 0; hf < 2; hf++) {
            int j = jb + hf * 8;
            size_t off0 = (((size_t)vc0 + c0) * HH + i) * WW + j;
            size_t off1 = off0 + HWS;
            float x0 = *(const float*)(smem + xbase + j * 4);
            float x1 = *(const float*)(smem + xbase + 512 + j * 4);
            out[off0] = gm * acc[ni][hf * 2 + 0] + x0;
            out[off1] = gm * acc[ni][hf * 2 + 1] + x1;
        }
    }
}

// ---------------------------------------------------------------------------
extern "C" void kernel_launch(void* const* d_in, const int* in_sizes, int n_in,
                              void* d_out, int out_size)
{
    const float* x     = (const float*)d_in[0];
    const float* Wq    = (const float*)d_in[1];
    const float* bq    = (const float*)d_in[2];
    const float* Wk    = (const float*)d_in[3];
    const float* bk    = (const float*)d_in[4];
    const float* Wv    = (const float*)d_in[5];
    const float* bv    = (const float*)d_in[6];
    const float* gamma = (const float*)d_in[7];
    float* out = (float*)d_out;

    cudaFuncSetAttribute(attn_kernel, cudaFuncAttributeMaxDynamicSharedMemorySize,
                         AT_SMEM);
    cudaFuncSetAttribute(proj_mma_kernel, cudaFuncAttributeMaxDynamicSharedMemorySize,
                         65536);

    cudaLaunchAttribute pdl[1];
    pdl[0].id = cudaLaunchAttributeProgrammaticStreamSerialization;
    pdl[0].val.programmaticStreamSerializationAllowed = 1;

    prep_w_kernel<<<384, 256>>>(Wq, Wk, Wv);
    prep_x_kernel<<<dim3(256, 4, NB), 256>>>(x);

    {   // proj: PDL-dependent on prep_x (waits in-kernel before global reads)
        cudaLaunchConfig_t cfg = {};
        cfg.gridDim = dim3(3, 128, NB);
        cfg.blockDim = dim3(256, 1, 1);
        cfg.dynamicSmemBytes = 65536;
        cfg.stream = 0;
        cfg.attrs = pdl;
        cfg.numAttrs = 1;
        cudaLaunchKernelEx(&cfg, proj_mma_kernel, bq, bk, bv);
    }
    {   // transpose: PDL-dependent on proj (waits at top, then signals attn)
        cudaLaunchConfig_t cfg = {};
        cfg.gridDim = dim3(2, 2, 1536);
        cfg.blockDim = dim3(256, 1, 1);
        cfg.dynamicSmemBytes = 0;
        cfg.stream = 0;
        cfg.attrs = pdl;
        cfg.numAttrs = 1;
        cudaLaunchKernelEx(&cfg, transpose_kernel);
    }
    {   // attn: PDL-dependent on transpose (G1/G2 pre-wait; G3 gated)
        cudaLaunchConfig_t cfg = {};
        cfg.gridDim = dim3(HH, NB * 4, 1);
        cfg.blockDim = dim3(256, 1, 1);
        cfg.dynamicSmemBytes = AT_SMEM;
        cfg.stream = 0;
        cfg.attrs = pdl;
        cfg.numAttrs = 1;
        cudaLaunchKernelEx(&cfg, attn_kernel, x, gamma, out);
    }
}

// round 17
// speedup vs baseline: 1.0940x; 1.0266x over previous
#include <cuda_runtime.h>
#include <cuda_bf16.h>
#include <cuda_fp16.h>
#include <cstdint>

#define HH 128
#define WW 128
#define HWS 16384
#define NB 4
#define KP 512   // split-K storage: [hi(256) | lo(256)]; 12 virtual chunks at GEMM

// ---------------- scratch (device globals; allocation-free rule) ------------
__device__ __align__(16) __half g_qf [(size_t)NB * 32 * HWS];
__device__ __align__(16) __half g_kf [(size_t)NB * 32 * HWS];
__device__ __align__(16) __half g_qfT[(size_t)NB * 32 * HWS];
__device__ __align__(16) __half g_kfT[(size_t)NB * 32 * HWS];
__device__ __align__(16) __half g_v [(size_t)NB * 256 * HWS];
__device__ __align__(16) __half g_vT[(size_t)NB * 256 * HWS];
__device__ __align__(16) __nv_bfloat16 g_wsplit[(size_t)384 * KP];       // [m][hi|lo]
__device__ __align__(16) __nv_bfloat16 g_xt[(size_t)NB * HWS * KP];      // [b][p][hi|lo]

// single TU-wide dynamic smem symbol (char; cast per-kernel)
extern __shared__ __align__(1024) char smem_raw[];

static __device__ __forceinline__ uint32_t sw128(uint32_t off) {
    return off ^ ((off >> 3) & 0x70);
}
static __device__ __forceinline__ uint32_t sw256(uint32_t off) {
    return off ^ (((off >> 8) & 7) << 4);
}
__device__ __forceinline__ uint32_t smem_u32(const void* p) {
    uint32_t a;
    asm("{ .reg .u64 t; cvta.to.shared.u64 t, %1; cvt.u32.u64 %0, t; }"
        : "=r"(a) : "l"(p));
    return a;
}
__device__ __forceinline__ void ldmatrix_x4(uint32_t& r0, uint32_t& r1,
                                            uint32_t& r2, uint32_t& r3, uint32_t addr) {
    asm volatile("ldmatrix.sync.aligned.m8n8.x4.shared.b16 {%0,%1,%2,%3}, [%4];"
                 : "=r"(r0), "=r"(r1), "=r"(r2), "=r"(r3) : "r"(addr));
}
__device__ __forceinline__ void ldmatrix_x4_trans(uint32_t& r0, uint32_t& r1,
                                                  uint32_t& r2, uint32_t& r3, uint32_t addr) {
    asm volatile("ldmatrix.sync.aligned.m8n8.x4.trans.shared.b16 {%0,%1,%2,%3}, [%4];"
                 : "=r"(r0), "=r"(r1), "=r"(r2), "=r"(r3) : "r"(addr));
}
__device__ __forceinline__ void mma_bf16(float& d0, float& d1, float& d2, float& d3,
                                         uint32_t a0, uint32_t a1, uint32_t a2, uint32_t a3,
                                         uint32_t b0, uint32_t b1) {
    asm volatile("mma.sync.aligned.m16n8k16.row.col.f32.bf16.bf16.f32 "
                 "{%0,%1,%2,%3}, {%4,%5,%6,%7}, {%8,%9}, {%0,%1,%2,%3};"
                 : "+f"(d0), "+f"(d1), "+f"(d2), "+f"(d3)
                 : "r"(a0), "r"(a1), "r"(a2), "r"(a3), "r"(b0), "r"(b1));
}
__device__ __forceinline__ void mma_f16(float& d0, float& d1, float& d2, float& d3,
                                        uint32_t a0, uint32_t a1, uint32_t a2, uint32_t a3,
                                        uint32_t b0, uint32_t b1) {
    asm volatile("mma.sync.aligned.m16n8k16.row.col.f32.f16.f16.f32 "
                 "{%0,%1,%2,%3}, {%4,%5,%6,%7}, {%8,%9}, {%0,%1,%2,%3};"
                 : "+f"(d0), "+f"(d1), "+f"(d2), "+f"(d3)
                 : "r"(a0), "r"(a1), "r"(a2), "r"(a3), "r"(b0), "r"(b1));
}
#define CP_ASYNC16(dst, src) \
    asm volatile("cp.async.cg.shared.global [%0], [%1], 16;" :: "r"(dst), "l"(src))
#define CP_COMMIT() asm volatile("cp.async.commit_group;" ::: "memory")
#define CP_WAIT2()  asm volatile("cp.async.wait_group 2;" ::: "memory")
#define CP_WAIT1()  asm volatile("cp.async.wait_group 1;" ::: "memory")
#define CP_WAIT0()  asm volatile("cp.async.wait_group 0;" ::: "memory")
#define GDC_LAUNCH() asm volatile("griddepcontrol.launch_dependents;")
#define GDC_WAIT()   asm volatile("griddepcontrol.wait;" ::: "memory")

// ---------------------------------------------------------------------------
// prep_w: W' bf16 [384][512]; rows 0-255 Wv, 256-287 Wq, 288-319 Wk, 320-383 0
// ---------------------------------------------------------------------------
__global__ void prep_w_kernel(const float* __restrict__ Wq, const float* __restrict__ Wk,
                              const float* __restrict__ Wv)
{
    const int m = blockIdx.x;
    const int c = threadIdx.x;
    float w = 0.0f;
    if (m < 256)      w = Wv[m * 256 + c];
    else if (m < 288) w = Wq[(m - 256) * 256 + c];
    else if (m < 320) w = Wk[(m - 288) * 256 + c];
    __nv_bfloat16 hi = __float2bfloat16(w);
    __nv_bfloat16 lo = __float2bfloat16(w - __bfloat162float(hi));
    g_wsplit[(size_t)m * KP + c]       = hi;
    g_wsplit[(size_t)m * KP + 256 + c] = lo;
}

// ---------------------------------------------------------------------------
// prep_x: XT' bf16 [b][p][512]; signals proj (PDL) at top
// ---------------------------------------------------------------------------
__global__ void prep_x_kernel(const float* __restrict__ x)
{
    GDC_LAUNCH();
    __shared__ float sm[64][65];
    const int b = blockIdx.z, ct = blockIdx.y, pt = blockIdx.x;
    const int c0 = ct * 64, p0 = pt * 64;
    const int t = threadIdx.x;
    const int pj = t & 63, ci0 = t >> 6;
    const float* xb = x + ((size_t)b * 256 + c0) * HWS + p0;
    #pragma unroll
    for (int i = 0; i < 16; i++) {
        int ci = ci0 + i * 4;
        sm[ci][pj] = xb[(size_t)ci * HWS + pj];
    }
    __syncthreads();
    const int cp = t & 31, pl = t >> 5;
    #pragma unroll
    for (int i = 0; i < 8; i++) {
        int p = pl + i * 8;
        float f0 = sm[2 * cp][p], f1 = sm[2 * cp + 1][p];
        __nv_bfloat16 h0 = __float2bfloat16(f0), h1 = __float2bfloat16(f1);
        __nv_bfloat16 l0 = __float2bfloat16(f0 - __bfloat162float(h0));
        __nv_bfloat16 l1 = __float2bfloat16(f1 - __bfloat162float(h1));
        __nv_bfloat162 hp; hp.x = h0; hp.y = h1;
        __nv_bfloat162 lp; lp.x = l0; lp.y = l1;
        __nv_bfloat16* row = g_xt + ((size_t)b * HWS + p0 + p) * KP;
        *(__nv_bfloat162*)(row + c0 + 2 * cp)       = hp;
        *(__nv_bfloat162*)(row + 256 + c0 + 2 * cp) = lp;
    }
}

// ---------------------------------------------------------------------------
// proj_mma: 2-stage cp.async double-buffered bf16 mma GEMM; mt fastest.
// Epilogue: v fp16; q/k now SINGLE fp16 planes.
// ---------------------------------------------------------------------------
__constant__ int ACH[12] = {0, 1, 2, 3, 0, 1, 2, 3, 4, 5, 6, 7};
__constant__ int BCH[12] = {0, 1, 2, 3, 4, 5, 6, 7, 0, 1, 2, 3};

__global__ void __launch_bounds__(256) proj_mma_kernel(
    const float* __restrict__ bq, const float* __restrict__ bk,
    const float* __restrict__ bv)
{
    GDC_LAUNCH();
    char* smem = smem_raw;
    const uint32_t smem_base = smem_u32(smem);
    const int tid = threadIdx.x;
    const int wid = tid >> 5, lane = tid & 31;
    const int warp_m = wid & 1;
    const int warp_n = wid >> 1;
    const int mt = blockIdx.x, pt = blockIdx.y, b = blockIdx.z;
    const bool mma_active = (mt < 2) || (warp_m == 0);

    const char* Abase = (const char*)(g_wsplit + (size_t)mt * 128 * KP);
    const char* Bbase = (const char*)(g_xt + ((size_t)b * HWS + pt * 128) * KP);

    float acc[4][4][4];
    #pragma unroll
    for (int i = 0; i < 4; i++)
        #pragma unroll
        for (int j = 0; j < 4; j++)
            #pragma unroll
            for (int k = 0; k < 4; k++) acc[i][j][k] = 0.0f;

    const int a_row_in = lane & 15;
    const int a_kseg   = (lane >> 4) << 4;
    const int b_row_in = (lane & 7) + ((lane >> 4) << 3);
    const int b_kseg   = ((lane >> 3) & 1) << 4;

    const int ld_row = tid >> 3, ld_seg = tid & 7;

    auto issue = [&](int ch, int st) {
        const size_t a0b = (size_t)ACH[ch] * 128;
        const size_t b0b = (size_t)BCH[ch] * 128;
        const uint32_t sb = smem_base + st * 32768;
        #pragma unroll
        for (int r = 0; r < 4; r++) {
            int row = ld_row + r * 32;
            uint32_t so = sw128((uint32_t)(row * 128 + ld_seg * 16));
            CP_ASYNC16(sb + so,         Abase + (size_t)row * (KP * 2) + a0b + ld_seg * 16);
            CP_ASYNC16(sb + 16384 + so, Bbase + (size_t)row * (KP * 2) + b0b + ld_seg * 16);
        }
    };

    GDC_WAIT();   // g_xt (prep_x) ready; g_wsplit transitively ready
    issue(0, 0);
    CP_COMMIT();

    for (int ch = 0; ch < 12; ch++) {
        const int st = ch & 1;
        if (ch + 1 < 12) issue(ch + 1, st ^ 1);
        CP_COMMIT();
        CP_WAIT1();
        __syncthreads();

        if (mma_active) {
            const uint32_t sA_u = smem_base + st * 32768;
            const uint32_t sB_u = sA_u + 16384;
            #pragma unroll
            for (int kk = 0; kk < 4; kk++) {
                uint32_t af[4][4];
                #pragma unroll
                for (int mi = 0; mi < 4; mi++) {
                    int row = warp_m * 64 + mi * 16 + a_row_in;
                    ldmatrix_x4(af[mi][0], af[mi][1], af[mi][2], af[mi][3],
                                sA_u + sw128((uint32_t)(row * 128 + kk * 32 + a_kseg)));
                }
                uint32_t bf[2][4];
                #pragma unroll
                for (int ni16 = 0; ni16 < 2; ni16++) {
                    int row = warp_n * 32 + ni16 * 16 + b_row_in;
                    ldmatrix_x4(bf[ni16][0], bf[ni16][1], bf[ni16][2], bf[ni16][3],
                                sB_u + sw128((uint32_t)(row * 128 + kk * 32 + b_kseg)));
                }
                #pragma unroll
                for (int mi = 0; mi < 4; mi++)
                    #pragma unroll
                    for (int ni = 0; ni < 4; ni++)
                        mma_bf16(acc[mi][ni][0], acc[mi][ni][1], acc[mi][ni][2], acc[mi][ni][3],
                                 af[mi][0], af[mi][1], af[mi][2], af[mi][3],
                                 bf[ni >> 1][(ni & 1) * 2 + 0], bf[ni >> 1][(ni & 1) * 2 + 1]);
            }
        }
        __syncthreads();
    }

    const int p0 = pt * 128 + warp_n * 32 + 2 * (lane & 3);
    #pragma unroll
    for (int mi = 0; mi < 4; mi++) {
        #pragma unroll
        for (int half = 0; half < 2; half++) {
            int m = mt * 128 + warp_m * 64 + mi * 16 + (lane >> 2) + half * 8;
            #pragma unroll
            for (int ni = 0; ni < 4; ni++) {
                float v0 = acc[mi][ni][half * 2 + 0];
                float v1 = acc[mi][ni][half * 2 + 1];
                int p = p0 + ni * 8;
                if (m < 256) {
                    float bias = bv[m];
                    __half2 hv = __floats2half2_rn(v0 + bias, v1 + bias);
                    *(__half2*)&g_v[((size_t)b * 256 + m) * HWS + p] = hv;
                } else if (m < 320) {
                    const bool isq = (m < 288);
                    int c = isq ? (m - 256) : (m - 288);
                    float bias = isq ? bq[c] : bk[c];
                    __half2 hv = __floats2half2_rn(v0 + bias, v1 + bias);
                    size_t off = ((size_t)b * 32 + c) * HWS + p;
                    if (isq) *(__half2*)&g_qf[off] = hv;
                    else     *(__half2*)&g_kf[off] = hv;
                }
            }
        }
    }
}

// ---------------------------------------------------------------------------
// transpose: 16-bit planes [H][W] -> [W][H]. plane 0-127 qf, 128-255 kf,
// 256-1279 v. Waits for proj, then signals attn.
// ---------------------------------------------------------------------------
__global__ void transpose_kernel()
{
    GDC_WAIT();     // proj outputs complete
    GDC_LAUNCH();   // attn may launch (its G1/G2 only touch proj outputs)
    __shared__ uint16_t sm[64][70];
    const int plane = blockIdx.z;
    const uint16_t* src;
    uint16_t* dst;
    if (plane < 128) {
        src = (const uint16_t*)(g_qf + (size_t)plane * HWS);
        dst = (uint16_t*)(g_qfT + (size_t)plane * HWS);
    } else if (plane < 256) {
        src = (const uint16_t*)(g_kf + (size_t)(plane - 128) * HWS);
        dst = (uint16_t*)(g_kfT + (size_t)(plane - 128) * HWS);
    } else {
        int ch = plane - 256;
        src = (const uint16_t*)(g_v + (size_t)ch * HWS);
        dst = (uint16_t*)(g_vT + (size_t)ch * HWS);
    }
    const int ti = blockIdx.y * 64, tj = blockIdx.x * 64;
    const int t = threadIdx.x;
    const int cw = (t & 31) * 2, r0 = t >> 5;
    #pragma unroll
    for (int p = 0; p < 8; p++) {
        int r = r0 + p * 8;
        *(uint32_t*)&sm[r][cw] = *(const uint32_t*)&src[(size_t)(ti + r) * WW + tj + cw];
    }
    __syncthreads();
    const int ch2 = (t & 31) * 2, w0 = t >> 5;
    #pragma unroll
    for (int p = 0; p < 8; p++) {
        int w = w0 + p * 8;
        uint32_t v = (uint32_t)sm[ch2][w] | ((uint32_t)sm[ch2 + 1][w] << 16);
        *(uint32_t*)&dst[(size_t)(tj + w) * HH + ti + ch2] = v;
    }
}

// ---------------------------------------------------------------------------
// Tensor-core criss-cross attention; single-fp16 q/k energy (k=16: 8 data +
// 8 zero pad). smem: P 32K | V0 16K | V1 16K | A0 4K | A1 4K | B0 4K | B1 4K
// | ssum 1K = 81.9K. Direct-LDG epilogue.
// ---------------------------------------------------------------------------
#define AT_P    0
#define AT_V0   32768
#define AT_V1   49152
#define AT_A0   65536
#define AT_A1   69632
#define AT_B0   73728
#define AT_B1   77824
#define AT_SSUM 81920
#define AT_SMEM (81920 + 1024)

__global__ void __launch_bounds__(256, 2) attn_kernel(
    const float* __restrict__ x, const float* __restrict__ gamma,
    float* __restrict__ out)
{
    char* smem = smem_raw;
    float* ssum = (float*)(smem + AT_SSUM);

    const int i  = blockIdx.x;
    const int bh = blockIdx.y;
    const int b = bh >> 2, h = bh & 3;
    const int tid = threadIdx.x;
    const int wid = tid >> 5, lane = tid & 31;

    const uint32_t smb  = smem_u32(smem);
    const uint32_t sP_u = smb + AT_P;

    const int b_row_in = (lane & 7) + ((lane >> 4) << 3);
    const int b_kseg   = ((lane >> 3) & 1) << 4;
    const int tr_row_a = (lane & 7) + (((lane >> 4) & 1) << 3);
    const int tr_col_a = ((lane >> 3) & 1) << 3;
    const int tr_row_b = (lane & 7) + (((lane >> 3) & 1) << 3);
    const int tr_col_b = ((lane >> 4) & 1) << 3;

    const int em = wid & 1, en = wid >> 1;

    const int qkc0 = (b * 32 + h * 8);
    const int vc0  = (b * 256 + h * 64);
    const int loff = i * 128;

    // zero pad rows 8-15 of A0/A1/B0/B1 (k-rows 8..15; persist both phases)
    #pragma unroll
    for (int z = 0; z < 2; z++) {
        int idx = tid + z * 256;                  // 0..511
        int bufsel = idx >> 7;                    // 0:A0 1:A1 2:B0 3:B1
        int r = 8 + ((idx >> 4) & 7), chunk = idx & 15;
        uint32_t base = (bufsel == 0) ? AT_A0 : (bufsel == 1) ? AT_A1
                       : (bufsel == 2) ? AT_B0 : AT_B1;
        *(uint4*)(smem + base + sw256((uint32_t)(r * 256 + chunk * 16))) =
            make_uint4(0, 0, 0, 0);
    }

    auto issue_AB = [&](int ph) {
        const __half* Kf = ph ? g_kfT : g_kf;
        const __half* Qf = ph ? g_qfT : g_qf;
        const uint32_t aU = smb + (ph ? AT_A1 : AT_A0);
        const uint32_t bU = smb + (ph ? AT_B1 : AT_B0);
        // 256 loads: tiles A(K),B(Q), rows 0-7, 16 chunks each
        int idx = tid;
        int tile = idx >> 7;                      // 0: A, 1: B
        int r = (idx >> 4) & 7, chunk = idx & 15; // r == channel c
        const __half* src = tile ? Qf : Kf;
        const char* gsrc = (const char*)(src + (size_t)(qkc0 + r) * HWS + loff) + chunk * 16;
        uint32_t dst = (tile ? bU : aU) + sw256((uint32_t)(r * 256 + chunk * 16));
        CP_ASYNC16(dst, gsrc);
    };
    auto issue_V = [&](int ph) {
        const __half* Vp = ph ? g_vT : g_v;
        const uint32_t vU = smb + (ph ? AT_V1 : AT_V0);
        #pragma unroll
        for (int it = 0; it < 4; it++) {
            int idx = tid + it * 256;
            int c = idx >> 4, chunk = idx & 15;
            const char* gsrc = (const char*)(Vp + (size_t)(vc0 + c) * HWS + loff) + chunk * 16;
            CP_ASYNC16(vU + sw256((uint32_t)(c * 256 + chunk * 16)), gsrc);
        }
    };

    issue_AB(0); CP_COMMIT();                 // G1 (non-T: safe pre-wait)
    issue_V(0);  CP_COMMIT();                 // G2 (non-T: safe pre-wait)
    GDC_WAIT();                               // transpose done
    issue_AB(1); issue_V(1); CP_COMMIT();     // G3 (T planes)

    float acc[8][4];
    #pragma unroll
    for (int ni = 0; ni < 8; ni++)
        #pragma unroll
        for (int k = 0; k < 4; k++) acc[ni][k] = 0.0f;

    for (int phase = 0; phase < 2; phase++) {
        const uint32_t sA_u = smb + (phase ? AT_A1 : AT_A0);
        const uint32_t sB_u = smb + (phase ? AT_B1 : AT_B0);
        const uint32_t sV_u = smb + (phase ? AT_V1 : AT_V0);
        if (phase == 0) { CP_WAIT2(); } else { CP_WAIT0(); }
        __syncthreads();

        // ---- energy mma: single k=16 step, fp16 operands ----
        float ef[4][4][4];
        #pragma unroll
        for (int mi = 0; mi < 4; mi++)
            #pragma unroll
            for (int ni = 0; ni < 4; ni++)
                #pragma unroll
                for (int k = 0; k < 4; k++) ef[mi][ni][k] = 0.0f;
        {
            uint32_t af[4][4];
            #pragma unroll
            for (int mi = 0; mi < 4; mi++) {
                int col = em * 64 + mi * 16 + tr_col_a;
                ldmatrix_x4_trans(af[mi][0], af[mi][1], af[mi][2], af[mi][3],
                                  sA_u + sw256((uint32_t)(tr_row_a * 256 + col * 2)));
            }
            uint32_t bfr[2][4];
            #pragma unroll
            for (int n16 = 0; n16 < 2; n16++) {
                int col = en * 32 + n16 * 16 + tr_col_b;
                ldmatrix_x4_trans(bfr[n16][0], bfr[n16][1], bfr[n16][2], bfr[n16][3],
                                  sB_u + sw256((uint32_t)(tr_row_b * 256 + col * 2)));
            }
            #pragma unroll
            for (int mi = 0; mi < 4; mi++)
                #pragma unroll
                for (int ni = 0; ni < 4; ni++)
                    mma_f16(ef[mi][ni][0], ef[mi][ni][1], ef[mi][ni][2], ef[mi][ni][3],
                            af[mi][0], af[mi][1], af[mi][2], af[mi][3],
                            bfr[ni >> 1][(ni & 1) * 2 + 0], bfr[ni >> 1][(ni & 1) * 2 + 1]);
        }

        // ---- exp in registers + per-j column sums ----
        float psum[4][2];
        #pragma unroll
        for (int ni = 0; ni < 4; ni++) { psum[ni][0] = 0.0f; psum[ni][1] = 0.0f; }
        #pragma unroll
        for (int mi = 0; mi < 4; mi++)
            #pragma unroll
            for (int ni = 0; ni < 4; ni++) {
                ef[mi][ni][0] = __expf(ef[mi][ni][0]);
                ef[mi][ni][1] = __expf(ef[mi][ni][1]);
                ef[mi][ni][2] = __expf(ef[mi][ni][2]);
                ef[mi][ni][3] = __expf(ef[mi][ni][3]);
                psum[ni][0] += ef[mi][ni][0] + ef[mi][ni][2];
                psum[ni][1] += ef[mi][ni][1] + ef[mi][ni][3];
            }
        #pragma unroll
        for (int ni = 0; ni < 4; ni++) {
            #pragma unroll
            for (int d = 4; d <= 16; d <<= 1) {
                psum[ni][0] += __shfl_xor_sync(0xffffffffu, psum[ni][0], d);
                psum[ni][1] += __shfl_xor_sync(0xffffffffu, psum[ni][1], d);
            }
        }
        if ((lane >> 2) == 0) {
            #pragma unroll
            for (int ni = 0; ni < 4; ni++) {
                int j0 = en * 32 + ni * 8 + (lane & 3) * 2;
                *(float2*)&ssum[em * 128 + j0] = make_float2(psum[ni][0], psum[ni][1]);
            }
        }
        __syncthreads();

        // ---- normalize + store P fp16 [g][j] ----
        #pragma unroll
        for (int ni = 0; ni < 4; ni++) {
            int j0 = en * 32 + ni * 8 + (lane & 3) * 2;
            float2 sa = *(float2*)&ssum[j0];
            float2 sb = *(float2*)&ssum[128 + j0];
            float is0 = 1.0f / (sa.x + sb.x);
            float is1 = 1.0f / (sa.y + sb.y);
            #pragma unroll
            for (int mi = 0; mi < 4; mi++) {
                int g0 = em * 64 + mi * 16 + (lane >> 2);
                __half2 p0 = __floats2half2_rn(ef[mi][ni][0] * is0, ef[mi][ni][1] * is1);
                __half2 p1 = __floats2half2_rn(ef[mi][ni][2] * is0, ef[mi][ni][3] * is1);
                *(uint32_t*)(smem + AT_P + sw256((uint32_t)(g0 * 256 + j0 * 2)))       = *(uint32_t*)&p0;
                *(uint32_t*)(smem + AT_P + sw256((uint32_t)((g0 + 8) * 256 + j0 * 2))) = *(uint32_t*)&p1;
            }
        }
        if (phase == 0) CP_WAIT1();   // V0 arrived (G2)
        __syncthreads();

        // ---- O mma: A = P (m=j, k=g, trans), B = V (n=c, k=g) ----
        {
            #pragma unroll
            for (int ks = 0; ks < 8; ks++) {
                uint32_t af[4];
                {
                    int row = ks * 16 + tr_row_a;
                    int col = wid * 16 + tr_col_a;
                    ldmatrix_x4_trans(af[0], af[1], af[2], af[3],
                                      sP_u + sw256((uint32_t)(row * 256 + col * 2)));
                }
                uint32_t bfr[4][4];
                #pragma unroll
                for (int n16 = 0; n16 < 4; n16++) {
                    int row = n16 * 16 + b_row_in;
                    ldmatrix_x4(bfr[n16][0], bfr[n16][1], bfr[n16][2], bfr[n16][3],
                                sV_u + sw256((uint32_t)(row * 256 + ks * 32) + (uint32_t)b_kseg));
                }
                #pragma unroll
                for (int n16 = 0; n16 < 4; n16++)
                    #pragma unroll
                    for (int sub = 0; sub < 2; sub++)
                        mma_f16(acc[n16 * 2 + sub][0], acc[n16 * 2 + sub][1],
                                acc[n16 * 2 + sub][2], acc[n16 * 2 + sub][3],
                                af[0], af[1], af[2], af[3],
                                bfr[n16][sub * 2 + 0], bfr[n16][sub * 2 + 1]);
            }
        }
        __syncthreads();
    }

    // ---- epilogue: direct LDG x ----
    const float gm = gamma[0];
    const size_t bch = (size_t)b * 256 + h * 64;
    const int jb = wid * 16 + (lane >> 2);
    #pragma unroll
    for (int ni = 0; ni < 8; ni++) {
        int c0 = ni * 8 + (lane & 3) * 2;
        #pragma unroll
        for (int hf = 0; hf < 2; hf++) {
            int j = jb + hf * 8;
            size_t off0 = ((bch + c0) * HH + i) * WW + j;
            size_t off1 = off0 + HWS;
            out[off0] = gm * acc[ni][hf * 2 + 0] + x[off0];
            out[off1] = gm * acc[ni][hf * 2 + 1] + x[off1];
        }
    }
}

// ---------------------------------------------------------------------------
extern "C" void kernel_launch(void* const* d_in, const int* in_sizes, int n_in,
                              void* d_out, int out_size)
{
    const float* x     = (const float*)d_in[0];
    const float* Wq    = (const float*)d_in[1];
    const float* bq    = (const float*)d_in[2];
    const float* Wk    = (const float*)d_in[3];
    const float* bk    = (const float*)d_in[4];
    const float* Wv    = (const float*)d_in[5];
    const float* bv    = (const float*)d_in[6];
    const float* gamma = (const float*)d_in[7];
    float* out = (float*)d_out;

    cudaFuncSetAttribute(attn_kernel, cudaFuncAttributeMaxDynamicSharedMemorySize,
                         AT_SMEM);
    cudaFuncSetAttribute(proj_mma_kernel, cudaFuncAttributeMaxDynamicSharedMemorySize,
                         65536);

    cudaLaunchAttribute pdl[1];
    pdl[0].id = cudaLaunchAttributeProgrammaticStreamSerialization;
    pdl[0].val.programmaticStreamSerializationAllowed = 1;

    prep_w_kernel<<<384, 256>>>(Wq, Wk, Wv);
    prep_x_kernel<<<dim3(256, 4, NB), 256>>>(x);

    {   // proj: PDL-dependent on prep_x
        cudaLaunchConfig_t cfg = {};
        cfg.gridDim = dim3(3, 128, NB);
        cfg.blockDim = dim3(256, 1, 1);
        cfg.dynamicSmemBytes = 65536;
        cfg.stream = 0;
        cfg.attrs = pdl;
        cfg.numAttrs = 1;
        cudaLaunchKernelEx(&cfg, proj_mma_kernel, bq, bk, bv);
    }
    {   // transpose: PDL-dependent on proj (waits at top, then signals attn)
        cudaLaunchConfig_t cfg = {};
        cfg.gridDim = dim3(2, 2, 1280);
        cfg.blockDim = dim3(256, 1, 1);
        cfg.dynamicSmemBytes = 0;
        cfg.stream = 0;
        cfg.attrs = pdl;
        cfg.numAttrs = 1;
        cudaLaunchKernelEx(&cfg, transpose_kernel);
    }
    {   // attn: PDL-dependent on transpose (G1/G2 pre-wait; G3 gated)
        cudaLaunchConfig_t cfg = {};
        cfg.gridDim = dim3(HH, NB * 4, 1);
        cfg.blockDim = dim3(256, 1, 1);
        cfg.dynamicSmemBytes = AT_SMEM;
        cfg.stream = 0;
        cfg.attrs = pdl;
        cfg.numAttrs = 1;
        cudaLaunchKernelEx(&cfg, attn_kernel, x, gamma, out);
    }
}